// round 5
// baseline (speedup 1.0000x reference)
#include <cuda_runtime.h>
#include <math.h>

#define T 2048
#define B 64
#define H 512
#define D 256
#define G_BLOCKS 96
#define NITER (T + 2)

// ---- scratch ----
__device__ float g_xT[(size_t)T * D * B];
__device__ float g_xw0T[(size_t)T * H * B];
__device__ float g_h1T[2][H * B];
__device__ float g_h2T[2][H * B];
__device__ float g_zT[2][H * B];
__device__ unsigned g_cnt[3 * 32];
__device__ unsigned g_done;
__device__ unsigned g_bar_phase;

// ---- asm helpers ----
__device__ __forceinline__ void lds_v2u64(unsigned addr, unsigned long long& a,
                                          unsigned long long& b) {
    asm volatile("ld.shared.v2.u64 {%0,%1}, [%2];" : "=l"(a), "=l"(b) : "r"(addr));
}
__device__ __forceinline__ void lds_u64(unsigned addr, unsigned long long& a) {
    asm volatile("ld.shared.u64 %0, [%1];" : "=l"(a) : "r"(addr));
}
#define FMA2(acc, w, h) \
    asm("fma.rn.f32x2 %0, %1, %2, %0;" : "+l"(acc) : "l"(w), "l"(h))
__device__ __forceinline__ unsigned long long add2(unsigned long long a,
                                                   unsigned long long b) {
    unsigned long long d;
    asm("add.rn.f32x2 %0, %1, %2;" : "=l"(d) : "l"(a), "l"(b));
    return d;
}
__device__ __forceinline__ float2 unpack2(unsigned long long v) {
    float2 r;
    asm("mov.b64 {%0,%1}, %2;" : "=f"(r.x), "=f"(r.y) : "l"(v));
    return r;
}
__device__ __forceinline__ float tanh_fast(float v) {
    asm("tanh.approx.f32 %0, %0;" : "+f"(v));
    return v;
}

__global__ void k_zero() {
    int idx = blockIdx.x * 256 + threadIdx.x;
    if (idx < 2 * H * B) {
        ((float*)g_h1T)[idx] = 0.0f;
        ((float*)g_h2T)[idx] = 0.0f;
    }
}

__global__ void k_transpose(const float* __restrict__ x) {
    size_t n = (size_t)T * D * B;
    size_t stride = (size_t)gridDim.x * blockDim.x;
    for (size_t o = (size_t)blockIdx.x * blockDim.x + threadIdx.x; o < n; o += stride) {
        int b = (int)(o & 63);
        int d = (int)((o >> 6) & 255);
        int t = (int)(o >> 14);
        g_xT[o] = __ldg(x + ((((size_t)b * T + t) << 8) | d));
    }
}

// ---- phase 1 (unchanged) ----
__global__ void __launch_bounds__(256) k_xproj(const float* __restrict__ Wih0,
                                               const float* __restrict__ bih0,
                                               const float* __restrict__ bhh0) {
    extern __shared__ float sm[];
    float* sw = sm;
    float* sx = sm + 128 * 256;
    int t = blockIdx.x, hq = blockIdx.y;
    int tid = threadIdx.x;
    int bgrp = tid & 15, hsub = tid >> 4;

    {
        const float4* s4 = (const float4*)(Wih0 + (size_t)hq * 128 * 256);
        float4* d4 = (float4*)sw;
        #pragma unroll
        for (int r = 0; r < 32; r++) d4[tid + r * 256] = __ldg(s4 + tid + r * 256);
    }
    {
        const float4* s4 = (const float4*)(g_xT + (size_t)t * D * B);
        float4* d4 = (float4*)sx;
        #pragma unroll
        for (int r = 0; r < 16; r++) d4[tid + r * 256] = s4[tid + r * 256];
    }
    __syncthreads();

    float4 acc[8];
    #pragma unroll
    for (int j = 0; j < 8; j++) {
        int h = hq * 128 + j * 16 + hsub;
        float bv = __ldg(bih0 + h) + __ldg(bhh0 + h);
        acc[j] = make_float4(bv, bv, bv, bv);
    }
    const float4* sx4 = (const float4*)sx;
    #pragma unroll 4
    for (int k = 0; k < 256; k++) {
        float4 hv = sx4[k * 16 + bgrp];
        #pragma unroll
        for (int j = 0; j < 8; j++) {
            float w = sw[(j * 16 + hsub) * 256 + k];
            acc[j].x = fmaf(w, hv.x, acc[j].x);
            acc[j].y = fmaf(w, hv.y, acc[j].y);
            acc[j].z = fmaf(w, hv.z, acc[j].z);
            acc[j].w = fmaf(w, hv.w, acc[j].w);
        }
    }
    #pragma unroll
    for (int j = 0; j < 8; j++) {
        int h = hq * 128 + j * 16 + hsub;
        *((float4*)(g_xw0T + ((size_t)t * H + h) * B) + bgrp) = acc[j];
    }
}

// ---- phase 2: persistent 3-stage recurrence ----
// block = 32 rows x 32 batches; thread: ks=tid>>4 (32-k segment),
// rg=(tid>>2)&3 (8 rows), bg=tid&3 (8 batches). 32 f32x2 accumulators.
// smem: w 128KB  [k][16 rowpair-slots] f32x2 dup, slot=(rp+2*(kseg&1))&15
//       hbuf 64KB [k][8 b4-slots], slot=(b4+(kseg&1))&7  (red 64KB aliased)
__global__ void __launch_bounds__(256, 1) k_recur(const float* __restrict__ Whh0,
                                                  const float* __restrict__ Wih1,
                                                  const float* __restrict__ Whh1,
                                                  const float* __restrict__ bih1,
                                                  const float* __restrict__ bhh1) {
    extern __shared__ char smb[];
    const unsigned HB = 131072u;   // hbuf / red byte offset

    int stage = blockIdx.x >> 5;
    int sub = blockIdx.x & 31;
    int rowblk = sub >> 1;
    int bhalf = sub & 1;
    int h0 = rowblk * 32;
    int tid = threadIdx.x;
    int ks = tid >> 4;
    int rg = (tid >> 2) & 3;
    int bg = tid & 3;
    int sk1 = ks & 1;

    // ---- stage weights once with rotated rowpair slots ----
    const float* Wsrc = (stage == 0) ? Whh0 : (stage == 1) ? Wih1 : Whh1;
    const float* Wr = Wsrc + (size_t)h0 * 512;
    #pragma unroll
    for (int r = 0; r < 16; r++) {
        int idx = tid + r * 256;          // 0..4095 float4s (row = idx>>7, k4 = idx&127)
        int row = idx >> 7, k4 = idx & 127;
        float4 v = __ldg((const float4*)(Wr + (size_t)row * 512) + k4);
        int rp = row >> 1, lo = row & 1;
        float vv[4] = {v.x, v.y, v.z, v.w};
        #pragma unroll
        for (int j = 0; j < 4; j++) {
            int k = k4 * 4 + j;
            int slot = (rp + 2 * ((k >> 5) & 1)) & 15;
            *(float2*)(smb + k * 256 + slot * 16 + lo * 8) = make_float2(vv[j], vv[j]);
        }
    }

    unsigned smem_u32 = (unsigned)__cvta_generic_to_shared(smb);
    // per-thread constant slot offsets
    unsigned wo[4], oh[2];
    #pragma unroll
    for (int j = 0; j < 4; j++) wo[j] = (unsigned)(((rg * 4 + j + 2 * sk1) & 15) * 16);
    #pragma unroll
    for (int j = 0; j < 2; j++) oh[j] = (unsigned)(((bg * 2 + j + sk1) & 7) * 16);
    unsigned redb = smem_u32 + HB;

    // outputs: o0 = tid, o1 = tid+256 ; o = row*16 + bp
    int o0 = tid, o1 = tid + 256;
    int row0 = o0 >> 4, bp0 = o0 & 15;
    int row1 = o1 >> 4, bp1 = o1 & 15;
    float bias0 = 0.f, bias1 = 0.f;
    if (stage == 1) {
        bias0 = __ldg(bih1 + h0 + row0) + __ldg(bhh1 + h0 + row0);
        bias1 = __ldg(bih1 + h0 + row1) + __ldg(bhh1 + h0 + row1);
    }

    unsigned phase;
    asm volatile("ld.global.acquire.gpu.u32 %0, [%1];" : "=r"(phase) : "l"(&g_bar_phase) : "memory");
    __syncthreads();

    for (int i = 0; i < NITER; i++) {
        bool active = (stage == 0) ? (i < T) : (stage == 1) ? (i >= 1 && i <= T) : (i >= 2);
        if (active) {
            int t = i - stage;
            const float* src = (stage == 0) ? g_h1T[(t - 1) & 1]
                             : (stage == 1) ? g_h1T[t & 1]
                                            : g_h2T[(t - 1) & 1];
            const float4* s4 = (const float4*)src;

            // chunk 0 loads (k_local 0..15 of every kseg)
            float4 pf[8];
            int kidx[8], kb4[8];
            #pragma unroll
            for (int r = 0; r < 8; r++) {
                int f = tid + r * 256;
                int ki = f >> 3;
                kb4[r] = f & 7;
                kidx[r] = ((ki >> 4) << 5) | (ki & 15);   // + chunk*16
                pf[r] = __ldcg(s4 + kidx[r] * 16 + bhalf * 8 + kb4[r]);
            }
            float2 ex0, ex1;
            if (stage == 0) {
                ex0 = __ldcg((const float2*)(g_xw0T + ((size_t)t * H + h0 + row0) * B + bhalf * 32) + bp0);
                ex1 = __ldcg((const float2*)(g_xw0T + ((size_t)t * H + h0 + row1) * B + bhalf * 32) + bp1);
            } else if (stage == 2) {
                ex0 = __ldcg((const float2*)(g_zT[t & 1] + (h0 + row0) * B + bhalf * 32) + bp0);
                ex1 = __ldcg((const float2*)(g_zT[t & 1] + (h0 + row1) * B + bhalf * 32) + bp1);
            } else {
                ex0 = make_float2(bias0, bias0);
                ex1 = make_float2(bias1, bias1);
            }
            #pragma unroll
            for (int r = 0; r < 8; r++) {
                int k = kidx[r];
                int slot = (kb4[r] + ((k >> 5) & 1)) & 7;
                *(float4*)(smb + HB + k * 128 + slot * 16) = pf[r];
            }
            __syncthreads();
            // issue chunk1 LDG before computing chunk0
            #pragma unroll
            for (int r = 0; r < 8; r++)
                pf[r] = __ldcg(s4 + (kidx[r] + 16) * 16 + bhalf * 8 + kb4[r]);

            unsigned long long acc[32];
            #pragma unroll
            for (int j = 0; j < 32; j++) acc[j] = 0;

            #pragma unroll
            for (int c = 0; c < 2; c++) {
                unsigned kbase = (unsigned)(ks * 32 + c * 16);
                unsigned wa = smem_u32 + kbase * 256;
                unsigned ha = smem_u32 + HB + kbase * 128;
                #pragma unroll 4
                for (int j = 0; j < 16; j++) {
                    unsigned long long w0, w1, w2, w3, w4, w5, w6, w7;
                    unsigned long long hA, hB2, hC, hD;
                    lds_v2u64(wa + wo[0], w0, w1);
                    lds_v2u64(wa + wo[1], w2, w3);
                    lds_v2u64(wa + wo[2], w4, w5);
                    lds_v2u64(wa + wo[3], w6, w7);
                    lds_v2u64(ha + oh[0], hA, hB2);
                    lds_v2u64(ha + oh[1], hC, hD);
                    FMA2(acc[0],  w0, hA); FMA2(acc[1],  w0, hB2);
                    FMA2(acc[2],  w0, hC); FMA2(acc[3],  w0, hD);
                    FMA2(acc[4],  w1, hA); FMA2(acc[5],  w1, hB2);
                    FMA2(acc[6],  w1, hC); FMA2(acc[7],  w1, hD);
                    FMA2(acc[8],  w2, hA); FMA2(acc[9],  w2, hB2);
                    FMA2(acc[10], w2, hC); FMA2(acc[11], w2, hD);
                    FMA2(acc[12], w3, hA); FMA2(acc[13], w3, hB2);
                    FMA2(acc[14], w3, hC); FMA2(acc[15], w3, hD);
                    FMA2(acc[16], w4, hA); FMA2(acc[17], w4, hB2);
                    FMA2(acc[18], w4, hC); FMA2(acc[19], w4, hD);
                    FMA2(acc[20], w5, hA); FMA2(acc[21], w5, hB2);
                    FMA2(acc[22], w5, hC); FMA2(acc[23], w5, hD);
                    FMA2(acc[24], w6, hA); FMA2(acc[25], w6, hB2);
                    FMA2(acc[26], w6, hC); FMA2(acc[27], w6, hD);
                    FMA2(acc[28], w7, hA); FMA2(acc[29], w7, hB2);
                    FMA2(acc[30], w7, hC); FMA2(acc[31], w7, hD);
                    wa += 256; ha += 128;
                }
                if (c == 0) {   // publish chunk1 (disjoint k rows; WAR-safe)
                    #pragma unroll
                    for (int r = 0; r < 8; r++) {
                        int k = kidx[r] + 16;
                        int slot = (kb4[r] + ((k >> 5) & 1)) & 7;
                        *(float4*)(smb + HB + k * 128 + slot * 16) = pf[r];
                    }
                    __syncthreads();
                }
            }
            __syncthreads();   // hbuf dead -> red aliases

            // partials: red[ks][o], o = row*16 + bp
            #pragma unroll
            for (int r = 0; r < 8; r++) {
                int row = rg * 8 + r;
                unsigned a = redb + (unsigned)(ks * 4096 + row * 128 + bg * 32);
                asm volatile("st.shared.v2.u64 [%0], {%1,%2};"
                             :: "r"(a), "l"(acc[r * 4 + 0]), "l"(acc[r * 4 + 1]));
                asm volatile("st.shared.v2.u64 [%0+16], {%1,%2};"
                             :: "r"(a), "l"(acc[r * 4 + 2]), "l"(acc[r * 4 + 3]));
            }
            __syncthreads();

            unsigned long long s0a = 0, s0b = 0, s1a = 0, s1b = 0;
            #pragma unroll
            for (int kseg = 0; kseg < 16; kseg += 2) {
                unsigned long long p0, p1, p2, p3;
                lds_u64(redb + (unsigned)(kseg * 4096 + o0 * 8), p0);
                lds_u64(redb + (unsigned)(kseg * 4096 + o1 * 8), p1);
                lds_u64(redb + (unsigned)((kseg + 1) * 4096 + o0 * 8), p2);
                lds_u64(redb + (unsigned)((kseg + 1) * 4096 + o1 * 8), p3);
                s0a = add2(s0a, p0); s1a = add2(s1a, p1);
                s0b = add2(s0b, p2); s1b = add2(s1b, p3);
            }
            float2 f0 = unpack2(add2(s0a, s0b)), f1 = unpack2(add2(s1a, s1b));
            f0.x += ex0.x; f0.y += ex0.y;
            f1.x += ex1.x; f1.y += ex1.y;
            if (stage != 1) {
                f0.x = tanh_fast(f0.x); f0.y = tanh_fast(f0.y);
                f1.x = tanh_fast(f1.x); f1.y = tanh_fast(f1.y);
            }
            float* dst = (stage == 0) ? g_h1T[t & 1] : (stage == 1) ? g_zT[t & 1] : g_h2T[t & 1];
            __stcg((float2*)(dst + (h0 + row0) * B + bhalf * 32) + bp0, f0);
            __stcg((float2*)(dst + (h0 + row1) * B + bhalf * 32) + bp1, f1);
        }
        // ---- two-level release/acquire grid barrier ----
        __syncthreads();
        if (tid == 0) {
            unsigned prev;
            asm volatile("atom.release.gpu.global.add.u32 %0, [%1], %2;"
                         : "=r"(prev) : "l"(&g_cnt[stage * 32]), "r"(1u) : "memory");
            bool released = false;
            if (prev == 31) {
                asm volatile("st.relaxed.gpu.global.u32 [%0], %1;"
                             :: "l"(&g_cnt[stage * 32]), "r"(0u) : "memory");
                unsigned p2;
                asm volatile("atom.release.gpu.global.add.u32 %0, [%1], %2;"
                             : "=r"(p2) : "l"(&g_done), "r"(1u) : "memory");
                if (p2 == 2) {
                    asm volatile("st.relaxed.gpu.global.u32 [%0], %1;"
                                 :: "l"(&g_done), "r"(0u) : "memory");
                    asm volatile("st.release.gpu.global.u32 [%0], %1;"
                                 :: "l"(&g_bar_phase), "r"(phase + 1) : "memory");
                    released = true;
                }
            }
            if (!released) {
                unsigned cur;
                do {
                    asm volatile("ld.global.acquire.gpu.u32 %0, [%1];"
                                 : "=r"(cur) : "l"(&g_bar_phase) : "memory");
                } while (cur == phase);
            }
        }
        __syncthreads();
        phase++;
    }
}

// ---- final FC + softmax ----
__global__ void k_fc(const float* __restrict__ fcw, const float* __restrict__ fcb,
                     float* __restrict__ out) {
    __shared__ float logits[64][2];
    int tid = threadIdx.x;
    int b = tid >> 1, c = tid & 1;
    const float* h2 = g_h2T[(T - 1) & 1];
    float acc = __ldg(fcb + c);
    for (int k = 0; k < 512; k++)
        acc = fmaf(h2[k * 64 + b], __ldg(fcw + c * 512 + k), acc);
    logits[b][c] = acc;
    __syncthreads();
    if (c == 0) {
        float l0 = logits[b][0], l1 = logits[b][1];
        float m = fmaxf(l0, l1);
        float e0 = expf(l0 - m), e1 = expf(l1 - m);
        float s = e0 + e1;
        out[b * 2 + 0] = e0 / s;
        out[b * 2 + 1] = e1 / s;
    }
}

extern "C" void kernel_launch(void* const* d_in, const int* in_sizes, int n_in,
                              void* d_out, int out_size) {
    const float* x    = (const float*)d_in[0];
    const float* Wih0 = (const float*)d_in[1];
    const float* Whh0 = (const float*)d_in[2];
    const float* bih0 = (const float*)d_in[3];
    const float* bhh0 = (const float*)d_in[4];
    const float* Wih1 = (const float*)d_in[5];
    const float* Whh1 = (const float*)d_in[6];
    const float* bih1 = (const float*)d_in[7];
    const float* bhh1 = (const float*)d_in[8];
    const float* fcw  = (const float*)d_in[9];
    const float* fcb  = (const float*)d_in[10];
    float* out = (float*)d_out;

    cudaFuncSetAttribute(k_xproj, cudaFuncAttributeMaxDynamicSharedMemorySize, 196608);
    cudaFuncSetAttribute(k_recur, cudaFuncAttributeMaxDynamicSharedMemorySize, 196608);

    k_zero<<<256, 256>>>();
    k_transpose<<<4096, 256>>>(x);
    k_xproj<<<dim3(2048, 4), 256, 196608>>>(Wih0, bih0, bhh0);
    k_recur<<<G_BLOCKS, 256, 196608>>>(Whh0, Wih1, Whh1, bih1, bhh1);
    k_fc<<<1, 128>>>(fcw, fcb, out);
}

// round 6
// speedup vs baseline: 1.0318x; 1.0318x over previous
#include <cuda_runtime.h>
#include <math.h>

#define T 2048
#define B 64
#define H 512
#define D 256
#define G_BLOCKS 96
#define NITER (T + 2)

// ---- scratch ----
__device__ float g_xT[(size_t)T * D * B];
__device__ float g_xw0T[(size_t)T * H * B];
__device__ float g_h1T[2][H * B];
__device__ float g_h2T[2][H * B];
__device__ float g_zT[2][H * B];
__device__ unsigned g_cnt[3 * 32];
__device__ unsigned g_done;
__device__ unsigned g_bar_phase;

// ---- asm helpers ----
__device__ __forceinline__ void lds_v2u64(unsigned addr, unsigned long long& a,
                                          unsigned long long& b) {
    asm volatile("ld.shared.v2.u64 {%0,%1}, [%2];" : "=l"(a), "=l"(b) : "r"(addr));
}
__device__ __forceinline__ void lds_u64(unsigned addr, unsigned long long& a) {
    asm volatile("ld.shared.u64 %0, [%1];" : "=l"(a) : "r"(addr));
}
__device__ __forceinline__ void sts_u64(unsigned addr, unsigned long long v) {
    asm volatile("st.shared.u64 [%0], %1;" :: "r"(addr), "l"(v));
}
#define FMA2(acc, w, h) \
    asm("fma.rn.f32x2 %0, %1, %2, %0;" : "+l"(acc) : "l"(w), "l"(h))
__device__ __forceinline__ unsigned long long add2(unsigned long long a,
                                                   unsigned long long b) {
    unsigned long long d;
    asm("add.rn.f32x2 %0, %1, %2;" : "=l"(d) : "l"(a), "l"(b));
    return d;
}
__device__ __forceinline__ float2 unpack2(unsigned long long v) {
    float2 r;
    asm("mov.b64 {%0,%1}, %2;" : "=f"(r.x), "=f"(r.y) : "l"(v));
    return r;
}
__device__ __forceinline__ unsigned long long pack_dup(float v) {
    unsigned long long r;
    asm("mov.b64 %0, {%1,%1};" : "=l"(r) : "f"(v));
    return r;
}
__device__ __forceinline__ float tanh_fast(float v) {
    asm("tanh.approx.f32 %0, %0;" : "+f"(v));
    return v;
}

__global__ void k_zero() {
    int idx = blockIdx.x * 256 + threadIdx.x;
    if (idx < 2 * H * B) {
        ((float*)g_h1T)[idx] = 0.0f;
        ((float*)g_h2T)[idx] = 0.0f;
    }
}

__global__ void k_transpose(const float* __restrict__ x) {
    size_t n = (size_t)T * D * B;
    size_t stride = (size_t)gridDim.x * blockDim.x;
    for (size_t o = (size_t)blockIdx.x * blockDim.x + threadIdx.x; o < n; o += stride) {
        int b = (int)(o & 63);
        int d = (int)((o >> 6) & 255);
        int t = (int)(o >> 14);
        g_xT[o] = __ldg(x + ((((size_t)b * T + t) << 8) | d));
    }
}

// ---- phase 1 (unchanged) ----
__global__ void __launch_bounds__(256) k_xproj(const float* __restrict__ Wih0,
                                               const float* __restrict__ bih0,
                                               const float* __restrict__ bhh0) {
    extern __shared__ float sm[];
    float* sw = sm;
    float* sx = sm + 128 * 256;
    int t = blockIdx.x, hq = blockIdx.y;
    int tid = threadIdx.x;
    int bgrp = tid & 15, hsub = tid >> 4;

    {
        const float4* s4 = (const float4*)(Wih0 + (size_t)hq * 128 * 256);
        float4* d4 = (float4*)sw;
        #pragma unroll
        for (int r = 0; r < 32; r++) d4[tid + r * 256] = __ldg(s4 + tid + r * 256);
    }
    {
        const float4* s4 = (const float4*)(g_xT + (size_t)t * D * B);
        float4* d4 = (float4*)sx;
        #pragma unroll
        for (int r = 0; r < 16; r++) d4[tid + r * 256] = s4[tid + r * 256];
    }
    __syncthreads();

    float4 acc[8];
    #pragma unroll
    for (int j = 0; j < 8; j++) {
        int h = hq * 128 + j * 16 + hsub;
        float bv = __ldg(bih0 + h) + __ldg(bhh0 + h);
        acc[j] = make_float4(bv, bv, bv, bv);
    }
    const float4* sx4 = (const float4*)sx;
    #pragma unroll 4
    for (int k = 0; k < 256; k++) {
        float4 hv = sx4[k * 16 + bgrp];
        #pragma unroll
        for (int j = 0; j < 8; j++) {
            float w = sw[(j * 16 + hsub) * 256 + k];
            acc[j].x = fmaf(w, hv.x, acc[j].x);
            acc[j].y = fmaf(w, hv.y, acc[j].y);
            acc[j].z = fmaf(w, hv.z, acc[j].z);
            acc[j].w = fmaf(w, hv.w, acc[j].w);
        }
    }
    #pragma unroll
    for (int j = 0; j < 8; j++) {
        int h = hq * 128 + j * 16 + hsub;
        *((float4*)(g_xw0T + ((size_t)t * H + h) * B) + bgrp) = acc[j];
    }
}

// ---- phase 2: persistent 3-stage recurrence, WEIGHTS IN REGISTERS ----
// block = 32 rows x 32 batches, 256 thr.
// thread: ks = tid>>5 (64-k segment), lane = row. Holds W[row][kseg] as 64
// packed {w,w} f32x2 regs. Per k: 8 broadcast LDS.128 (h, 32 batches) feed
// 16 FFMA2. smem: hbuf 64KB [k=512][32b]; red 32KB [ks=8][512 ull].
__global__ void __launch_bounds__(256, 1) k_recur(const float* __restrict__ Whh0,
                                                  const float* __restrict__ Wih1,
                                                  const float* __restrict__ Whh1,
                                                  const float* __restrict__ bih1,
                                                  const float* __restrict__ bhh1) {
    extern __shared__ char smb[];
    const unsigned RED = 65536u;

    int stage = blockIdx.x >> 5;
    int sub = blockIdx.x & 31;
    int rowblk = sub >> 1;
    int bhalf = sub & 1;
    int h0 = rowblk * 32;
    int tid = threadIdx.x;
    int ks = tid >> 5;       // 64-k segment
    int lane = tid & 31;     // compute row (local)

    // ---- weights into registers: w[j] = {W[h0+lane][ks*64+j]} duplicated ----
    const float* Wsrc = (stage == 0) ? Whh0 : (stage == 1) ? Wih1 : Whh1;
    unsigned long long w[64];
    {
        const float4* wr4 = (const float4*)(Wsrc + (size_t)(h0 + lane) * 512 + ks * 64);
        #pragma unroll
        for (int r = 0; r < 16; r++) {
            float4 v = __ldg(wr4 + r);
            w[r * 4 + 0] = pack_dup(v.x);
            w[r * 4 + 1] = pack_dup(v.y);
            w[r * 4 + 2] = pack_dup(v.z);
            w[r * 4 + 3] = pack_dup(v.w);
        }
    }

    unsigned smem_u32 = (unsigned)__cvta_generic_to_shared(smb);
    unsigned hseg = smem_u32 + (unsigned)(ks * 64 * 128);
    unsigned redb = smem_u32 + RED;

    // outputs: o0 = tid -> (row0 = tid>>4, p0 = tid&15); o1 = o0+256 -> row0+16
    int row0 = tid >> 4, p0 = tid & 15;
    int row1 = row0 + 16;
    float bias0 = 0.f, bias1 = 0.f;
    if (stage == 1) {
        bias0 = __ldg(bih1 + h0 + row0) + __ldg(bhh1 + h0 + row0);
        bias1 = __ldg(bih1 + h0 + row1) + __ldg(bhh1 + h0 + row1);
    }
    // rotated reduction slots (conflict-avoiding): s = (p + row + (row>>4)*8) & 15
    int sst[16];
    #pragma unroll
    for (int p = 0; p < 16; p++)
        sst[p] = (p + lane + ((lane >> 4) << 3)) & 15;
    int s0 = (p0 + row0 + ((row0 >> 4) << 3)) & 15;
    int s1 = (p0 + row1 + ((row1 >> 4) << 3)) & 15;

    unsigned phase;
    asm volatile("ld.global.acquire.gpu.u32 %0, [%1];" : "=r"(phase) : "l"(&g_bar_phase) : "memory");
    __syncthreads();

    for (int i = 0; i < NITER; i++) {
        bool active = (stage == 0) ? (i < T) : (stage == 1) ? (i >= 1 && i <= T) : (i >= 2);
        if (active) {
            int t = i - stage;
            const float* src = (stage == 0) ? g_h1T[(t - 1) & 1]
                             : (stage == 1) ? g_h1T[t & 1]
                                            : g_h2T[(t - 1) & 1];
            const float4* s4 = (const float4*)src;

            // ---- stage h (64KB) in 2 groups of 8 float4/thread ----
            #pragma unroll
            for (int g = 0; g < 2; g++) {
                float4 pf[8];
                #pragma unroll
                for (int r = 0; r < 8; r++) {
                    int m = tid + (g * 8 + r) * 256;
                    pf[r] = __ldcg(s4 + (m >> 3) * 16 + bhalf * 8 + (m & 7));
                }
                #pragma unroll
                for (int r = 0; r < 8; r++) {
                    int m = tid + (g * 8 + r) * 256;
                    *(float4*)(smb + (m >> 3) * 128 + (m & 7) * 16) = pf[r];
                }
            }
            float2 ex0, ex1;
            if (stage == 0) {
                ex0 = __ldcg((const float2*)(g_xw0T + ((size_t)t * H + h0 + row0) * B + bhalf * 32) + p0);
                ex1 = __ldcg((const float2*)(g_xw0T + ((size_t)t * H + h0 + row1) * B + bhalf * 32) + p0);
            } else if (stage == 2) {
                ex0 = __ldcg((const float2*)(g_zT[t & 1] + (h0 + row0) * B + bhalf * 32) + p0);
                ex1 = __ldcg((const float2*)(g_zT[t & 1] + (h0 + row1) * B + bhalf * 32) + p0);
            } else {
                ex0 = make_float2(bias0, bias0);
                ex1 = make_float2(bias1, bias1);
            }
            __syncthreads();

            // ---- body: 64 k x (8 broadcast LDS.128 + 16 FFMA2) ----
            unsigned long long acc[16];
            #pragma unroll
            for (int p = 0; p < 16; p++) acc[p] = 0;
            unsigned ha = hseg;
            #pragma unroll
            for (int j = 0; j < 64; j++) {
                unsigned long long hv[16];
                lds_v2u64(ha +  0, hv[0],  hv[1]);
                lds_v2u64(ha + 16, hv[2],  hv[3]);
                lds_v2u64(ha + 32, hv[4],  hv[5]);
                lds_v2u64(ha + 48, hv[6],  hv[7]);
                lds_v2u64(ha + 64, hv[8],  hv[9]);
                lds_v2u64(ha + 80, hv[10], hv[11]);
                lds_v2u64(ha + 96, hv[12], hv[13]);
                lds_v2u64(ha + 112, hv[14], hv[15]);
                #pragma unroll
                for (int p = 0; p < 16; p++) FMA2(acc[p], w[j], hv[p]);
                ha += 128;
            }

            // ---- partials to red[ks][lane*16 + rotated slot] ----
            #pragma unroll
            for (int p = 0; p < 16; p++)
                sts_u64(redb + (unsigned)((ks * 512 + lane * 16 + sst[p]) * 8), acc[p]);
            __syncthreads();

            // ---- reduce 8 partials for outputs (row0,p0) and (row1,p0) ----
            unsigned long long s0a = 0, s0b = 0, s1a = 0, s1b = 0;
            #pragma unroll
            for (int kseg = 0; kseg < 8; kseg += 2) {
                unsigned long long q0, q1, q2, q3;
                lds_u64(redb + (unsigned)((kseg * 512 + row0 * 16 + s0) * 8), q0);
                lds_u64(redb + (unsigned)((kseg * 512 + row1 * 16 + s1) * 8), q1);
                lds_u64(redb + (unsigned)(((kseg + 1) * 512 + row0 * 16 + s0) * 8), q2);
                lds_u64(redb + (unsigned)(((kseg + 1) * 512 + row1 * 16 + s1) * 8), q3);
                s0a = add2(s0a, q0); s1a = add2(s1a, q1);
                s0b = add2(s0b, q2); s1b = add2(s1b, q3);
            }
            float2 f0 = unpack2(add2(s0a, s0b)), f1 = unpack2(add2(s1a, s1b));
            f0.x += ex0.x; f0.y += ex0.y;
            f1.x += ex1.x; f1.y += ex1.y;
            if (stage != 1) {
                f0.x = tanh_fast(f0.x); f0.y = tanh_fast(f0.y);
                f1.x = tanh_fast(f1.x); f1.y = tanh_fast(f1.y);
            }
            float* dst = (stage == 0) ? g_h1T[t & 1] : (stage == 1) ? g_zT[t & 1] : g_h2T[t & 1];
            __stcg((float2*)(dst + (h0 + row0) * B + bhalf * 32) + p0, f0);
            __stcg((float2*)(dst + (h0 + row1) * B + bhalf * 32) + p0, f1);
        }
        // ---- two-level release/acquire grid barrier ----
        __syncthreads();
        if (tid == 0) {
            unsigned prev;
            asm volatile("atom.release.gpu.global.add.u32 %0, [%1], %2;"
                         : "=r"(prev) : "l"(&g_cnt[stage * 32]), "r"(1u) : "memory");
            bool released = false;
            if (prev == 31) {
                asm volatile("st.relaxed.gpu.global.u32 [%0], %1;"
                             :: "l"(&g_cnt[stage * 32]), "r"(0u) : "memory");
                unsigned p2;
                asm volatile("atom.release.gpu.global.add.u32 %0, [%1], %2;"
                             : "=r"(p2) : "l"(&g_done), "r"(1u) : "memory");
                if (p2 == 2) {
                    asm volatile("st.relaxed.gpu.global.u32 [%0], %1;"
                                 :: "l"(&g_done), "r"(0u) : "memory");
                    asm volatile("st.release.gpu.global.u32 [%0], %1;"
                                 :: "l"(&g_bar_phase), "r"(phase + 1) : "memory");
                    released = true;
                }
            }
            if (!released) {
                unsigned cur;
                do {
                    asm volatile("ld.global.acquire.gpu.u32 %0, [%1];"
                                 : "=r"(cur) : "l"(&g_bar_phase) : "memory");
                } while (cur == phase);
            }
        }
        __syncthreads();
        phase++;
    }
}

// ---- final FC + softmax ----
__global__ void k_fc(const float* __restrict__ fcw, const float* __restrict__ fcb,
                     float* __restrict__ out) {
    __shared__ float logits[64][2];
    int tid = threadIdx.x;
    int b = tid >> 1, c = tid & 1;
    const float* h2 = g_h2T[(T - 1) & 1];
    float acc = __ldg(fcb + c);
    for (int k = 0; k < 512; k++)
        acc = fmaf(h2[k * 64 + b], __ldg(fcw + c * 512 + k), acc);
    logits[b][c] = acc;
    __syncthreads();
    if (c == 0) {
        float l0 = logits[b][0], l1 = logits[b][1];
        float m = fmaxf(l0, l1);
        float e0 = expf(l0 - m), e1 = expf(l1 - m);
        float s = e0 + e1;
        out[b * 2 + 0] = e0 / s;
        out[b * 2 + 1] = e1 / s;
    }
}

extern "C" void kernel_launch(void* const* d_in, const int* in_sizes, int n_in,
                              void* d_out, int out_size) {
    const float* x    = (const float*)d_in[0];
    const float* Wih0 = (const float*)d_in[1];
    const float* Whh0 = (const float*)d_in[2];
    const float* bih0 = (const float*)d_in[3];
    const float* bhh0 = (const float*)d_in[4];
    const float* Wih1 = (const float*)d_in[5];
    const float* Whh1 = (const float*)d_in[6];
    const float* bih1 = (const float*)d_in[7];
    const float* bhh1 = (const float*)d_in[8];
    const float* fcw  = (const float*)d_in[9];
    const float* fcb  = (const float*)d_in[10];
    float* out = (float*)d_out;

    cudaFuncSetAttribute(k_xproj, cudaFuncAttributeMaxDynamicSharedMemorySize, 196608);
    cudaFuncSetAttribute(k_recur, cudaFuncAttributeMaxDynamicSharedMemorySize, 98304);

    k_zero<<<256, 256>>>();
    k_transpose<<<4096, 256>>>(x);
    k_xproj<<<dim3(2048, 4), 256, 196608>>>(Wih0, bih0, bhh0);
    k_recur<<<G_BLOCKS, 256, 98304>>>(Whh0, Wih1, Whh1, bih1, bhh1);
    k_fc<<<1, 128>>>(fcw, fcb, out);
}

// round 7
// speedup vs baseline: 1.0358x; 1.0039x over previous
#include <cuda_runtime.h>
#include <math.h>

#define T 2048
#define B 64
#define H 512
#define D 256
#define G_BLOCKS 96
#define NITER (T + 2)

// ---- scratch ----
__device__ float g_xT[(size_t)T * D * B];
__device__ float g_xw0T[(size_t)T * H * B];
__device__ float g_h1T[2][H * B];
__device__ float g_h2T[2][H * B];
__device__ float g_zT[2][H * B];
__device__ unsigned g_cnt[3 * 32];
__device__ unsigned g_done;
__device__ unsigned g_bar_phase;

// ---- asm helpers ----
__device__ __forceinline__ void lds_v2u64(unsigned addr, unsigned long long& a,
                                          unsigned long long& b) {
    asm volatile("ld.shared.v2.u64 {%0,%1}, [%2];" : "=l"(a), "=l"(b) : "r"(addr));
}
__device__ __forceinline__ void lds_u64(unsigned addr, unsigned long long& a) {
    asm volatile("ld.shared.u64 %0, [%1];" : "=l"(a) : "r"(addr));
}
__device__ __forceinline__ void sts_u64(unsigned addr, unsigned long long v) {
    asm volatile("st.shared.u64 [%0], %1;" :: "r"(addr), "l"(v));
}
#define FMA2(acc, w, h) \
    asm("fma.rn.f32x2 %0, %1, %2, %0;" : "+l"(acc) : "l"(w), "l"(h))
__device__ __forceinline__ unsigned long long add2(unsigned long long a,
                                                   unsigned long long b) {
    unsigned long long d;
    asm("add.rn.f32x2 %0, %1, %2;" : "=l"(d) : "l"(a), "l"(b));
    return d;
}
__device__ __forceinline__ float2 unpack2(unsigned long long v) {
    float2 r;
    asm("mov.b64 {%0,%1}, %2;" : "=f"(r.x), "=f"(r.y) : "l"(v));
    return r;
}
__device__ __forceinline__ unsigned long long pack_dup(float v) {
    unsigned long long r;
    asm("mov.b64 %0, {%1,%1};" : "=l"(r) : "f"(v));
    return r;
}
__device__ __forceinline__ float tanh_fast(float v) {
    asm("tanh.approx.f32 %0, %0;" : "+f"(v));
    return v;
}

__global__ void k_zero() {
    int idx = blockIdx.x * 256 + threadIdx.x;
    if (idx < 2 * H * B) {
        ((float*)g_h1T)[idx] = 0.0f;
        ((float*)g_h2T)[idx] = 0.0f;
    }
}

__global__ void k_transpose(const float* __restrict__ x) {
    size_t n = (size_t)T * D * B;
    size_t stride = (size_t)gridDim.x * blockDim.x;
    for (size_t o = (size_t)blockIdx.x * blockDim.x + threadIdx.x; o < n; o += stride) {
        int b = (int)(o & 63);
        int d = (int)((o >> 6) & 255);
        int t = (int)(o >> 14);
        g_xT[o] = __ldg(x + ((((size_t)b * T + t) << 8) | d));
    }
}

// ---- phase 1 (unchanged) ----
__global__ void __launch_bounds__(256) k_xproj(const float* __restrict__ Wih0,
                                               const float* __restrict__ bih0,
                                               const float* __restrict__ bhh0) {
    extern __shared__ float sm[];
    float* sw = sm;
    float* sx = sm + 128 * 256;
    int t = blockIdx.x, hq = blockIdx.y;
    int tid = threadIdx.x;
    int bgrp = tid & 15, hsub = tid >> 4;

    {
        const float4* s4 = (const float4*)(Wih0 + (size_t)hq * 128 * 256);
        float4* d4 = (float4*)sw;
        #pragma unroll
        for (int r = 0; r < 32; r++) d4[tid + r * 256] = __ldg(s4 + tid + r * 256);
    }
    {
        const float4* s4 = (const float4*)(g_xT + (size_t)t * D * B);
        float4* d4 = (float4*)sx;
        #pragma unroll
        for (int r = 0; r < 16; r++) d4[tid + r * 256] = s4[tid + r * 256];
    }
    __syncthreads();

    float4 acc[8];
    #pragma unroll
    for (int j = 0; j < 8; j++) {
        int h = hq * 128 + j * 16 + hsub;
        float bv = __ldg(bih0 + h) + __ldg(bhh0 + h);
        acc[j] = make_float4(bv, bv, bv, bv);
    }
    const float4* sx4 = (const float4*)sx;
    #pragma unroll 4
    for (int k = 0; k < 256; k++) {
        float4 hv = sx4[k * 16 + bgrp];
        #pragma unroll
        for (int j = 0; j < 8; j++) {
            float w = sw[(j * 16 + hsub) * 256 + k];
            acc[j].x = fmaf(w, hv.x, acc[j].x);
            acc[j].y = fmaf(w, hv.y, acc[j].y);
            acc[j].z = fmaf(w, hv.z, acc[j].z);
            acc[j].w = fmaf(w, hv.w, acc[j].w);
        }
    }
    #pragma unroll
    for (int j = 0; j < 8; j++) {
        int h = hq * 128 + j * 16 + hsub;
        *((float4*)(g_xw0T + ((size_t)t * H + h) * B) + bgrp) = acc[j];
    }
}

// ---- phase 2: persistent 3-stage recurrence, WEIGHTS IN REGISTERS ----
// block = 32 rows x 32 batches, 256 thr.
// thread: ks = tid>>5 (64-k segment), lane = row. Holds W[row][kseg] as 64
// packed {w,w} f32x2 regs. Per k: 8 broadcast LDS.128 (h, 32 batches) feed
// 16 FFMA2. smem: hbuf 64KB [k=512][32b]; red 32KB [ks=8][512 ull].
__global__ void __launch_bounds__(256, 1) k_recur(const float* __restrict__ Whh0,
                                                  const float* __restrict__ Wih1,
                                                  const float* __restrict__ Whh1,
                                                  const float* __restrict__ bih1,
                                                  const float* __restrict__ bhh1) {
    extern __shared__ char smb[];
    const unsigned RED = 65536u;

    int stage = blockIdx.x >> 5;
    int sub = blockIdx.x & 31;
    int rowblk = sub >> 1;
    int bhalf = sub & 1;
    int h0 = rowblk * 32;
    int tid = threadIdx.x;
    int ks = tid >> 5;       // 64-k segment
    int lane = tid & 31;     // compute row (local)

    // ---- weights into registers: w[j] = {W[h0+lane][ks*64+j]} duplicated ----
    const float* Wsrc = (stage == 0) ? Whh0 : (stage == 1) ? Wih1 : Whh1;
    unsigned long long w[64];
    {
        const float4* wr4 = (const float4*)(Wsrc + (size_t)(h0 + lane) * 512 + ks * 64);
        #pragma unroll
        for (int r = 0; r < 16; r++) {
            float4 v = __ldg(wr4 + r);
            w[r * 4 + 0] = pack_dup(v.x);
            w[r * 4 + 1] = pack_dup(v.y);
            w[r * 4 + 2] = pack_dup(v.z);
            w[r * 4 + 3] = pack_dup(v.w);
        }
    }

    unsigned smem_u32 = (unsigned)__cvta_generic_to_shared(smb);
    unsigned hseg = smem_u32 + (unsigned)(ks * 64 * 128);
    unsigned redb = smem_u32 + RED;

    // outputs: o0 = tid -> (row0 = tid>>4, p0 = tid&15); o1 = o0+256 -> row0+16
    int row0 = tid >> 4, p0 = tid & 15;
    int row1 = row0 + 16;
    float bias0 = 0.f, bias1 = 0.f;
    if (stage == 1) {
        bias0 = __ldg(bih1 + h0 + row0) + __ldg(bhh1 + h0 + row0);
        bias1 = __ldg(bih1 + h0 + row1) + __ldg(bhh1 + h0 + row1);
    }
    // rotated reduction slots (conflict-avoiding): s = (p + row + (row>>4)*8) & 15
    int sst[16];
    #pragma unroll
    for (int p = 0; p < 16; p++)
        sst[p] = (p + lane + ((lane >> 4) << 3)) & 15;
    int s0 = (p0 + row0 + ((row0 >> 4) << 3)) & 15;
    int s1 = (p0 + row1 + ((row1 >> 4) << 3)) & 15;

    unsigned phase;
    asm volatile("ld.global.acquire.gpu.u32 %0, [%1];" : "=r"(phase) : "l"(&g_bar_phase) : "memory");
    __syncthreads();

    for (int i = 0; i < NITER; i++) {
        bool active = (stage == 0) ? (i < T) : (stage == 1) ? (i >= 1 && i <= T) : (i >= 2);
        if (active) {
            int t = i - stage;
            const float* src = (stage == 0) ? g_h1T[(t - 1) & 1]
                             : (stage == 1) ? g_h1T[t & 1]
                                            : g_h2T[(t - 1) & 1];
            const float4* s4 = (const float4*)src;

            // ---- stage h (64KB) in 2 groups of 8 float4/thread ----
            #pragma unroll
            for (int g = 0; g < 2; g++) {
                float4 pf[8];
                #pragma unroll
                for (int r = 0; r < 8; r++) {
                    int m = tid + (g * 8 + r) * 256;
                    pf[r] = __ldcg(s4 + (m >> 3) * 16 + bhalf * 8 + (m & 7));
                }
                #pragma unroll
                for (int r = 0; r < 8; r++) {
                    int m = tid + (g * 8 + r) * 256;
                    *(float4*)(smb + (m >> 3) * 128 + (m & 7) * 16) = pf[r];
                }
            }
            float2 ex0, ex1;
            if (stage == 0) {
                ex0 = __ldcg((const float2*)(g_xw0T + ((size_t)t * H + h0 + row0) * B + bhalf * 32) + p0);
                ex1 = __ldcg((const float2*)(g_xw0T + ((size_t)t * H + h0 + row1) * B + bhalf * 32) + p0);
            } else if (stage == 2) {
                ex0 = __ldcg((const float2*)(g_zT[t & 1] + (h0 + row0) * B + bhalf * 32) + p0);
                ex1 = __ldcg((const float2*)(g_zT[t & 1] + (h0 + row1) * B + bhalf * 32) + p0);
            } else {
                ex0 = make_float2(bias0, bias0);
                ex1 = make_float2(bias1, bias1);
            }
            __syncthreads();

            // ---- body: 64 k x (8 broadcast LDS.128 + 16 FFMA2) ----
            unsigned long long acc[16];
            #pragma unroll
            for (int p = 0; p < 16; p++) acc[p] = 0;
            unsigned ha = hseg;
            #pragma unroll
            for (int j = 0; j < 64; j++) {
                unsigned long long hv[16];
                lds_v2u64(ha +  0, hv[0],  hv[1]);
                lds_v2u64(ha + 16, hv[2],  hv[3]);
                lds_v2u64(ha + 32, hv[4],  hv[5]);
                lds_v2u64(ha + 48, hv[6],  hv[7]);
                lds_v2u64(ha + 64, hv[8],  hv[9]);
                lds_v2u64(ha + 80, hv[10], hv[11]);
                lds_v2u64(ha + 96, hv[12], hv[13]);
                lds_v2u64(ha + 112, hv[14], hv[15]);
                #pragma unroll
                for (int p = 0; p < 16; p++) FMA2(acc[p], w[j], hv[p]);
                ha += 128;
            }

            // ---- partials to red[ks][lane*16 + rotated slot] ----
            #pragma unroll
            for (int p = 0; p < 16; p++)
                sts_u64(redb + (unsigned)((ks * 512 + lane * 16 + sst[p]) * 8), acc[p]);
            __syncthreads();

            // ---- reduce 8 partials for outputs (row0,p0) and (row1,p0) ----
            unsigned long long s0a = 0, s0b = 0, s1a = 0, s1b = 0;
            #pragma unroll
            for (int kseg = 0; kseg < 8; kseg += 2) {
                unsigned long long q0, q1, q2, q3;
                lds_u64(redb + (unsigned)((kseg * 512 + row0 * 16 + s0) * 8), q0);
                lds_u64(redb + (unsigned)((kseg * 512 + row1 * 16 + s1) * 8), q1);
                lds_u64(redb + (unsigned)(((kseg + 1) * 512 + row0 * 16 + s0) * 8), q2);
                lds_u64(redb + (unsigned)(((kseg + 1) * 512 + row1 * 16 + s1) * 8), q3);
                s0a = add2(s0a, q0); s1a = add2(s1a, q1);
                s0b = add2(s0b, q2); s1b = add2(s1b, q3);
            }
            float2 f0 = unpack2(add2(s0a, s0b)), f1 = unpack2(add2(s1a, s1b));
            f0.x += ex0.x; f0.y += ex0.y;
            f1.x += ex1.x; f1.y += ex1.y;
            if (stage != 1) {
                f0.x = tanh_fast(f0.x); f0.y = tanh_fast(f0.y);
                f1.x = tanh_fast(f1.x); f1.y = tanh_fast(f1.y);
            }
            float* dst = (stage == 0) ? g_h1T[t & 1] : (stage == 1) ? g_zT[t & 1] : g_h2T[t & 1];
            __stcg((float2*)(dst + (h0 + row0) * B + bhalf * 32) + p0, f0);
            __stcg((float2*)(dst + (h0 + row1) * B + bhalf * 32) + p0, f1);
        }
        // ---- two-level release/acquire grid barrier ----
        __syncthreads();
        if (tid == 0) {
            unsigned prev;
            asm volatile("atom.release.gpu.global.add.u32 %0, [%1], %2;"
                         : "=r"(prev) : "l"(&g_cnt[stage * 32]), "r"(1u) : "memory");
            bool released = false;
            if (prev == 31) {
                asm volatile("st.relaxed.gpu.global.u32 [%0], %1;"
                             :: "l"(&g_cnt[stage * 32]), "r"(0u) : "memory");
                unsigned p2;
                asm volatile("atom.release.gpu.global.add.u32 %0, [%1], %2;"
                             : "=r"(p2) : "l"(&g_done), "r"(1u) : "memory");
                if (p2 == 2) {
                    asm volatile("st.relaxed.gpu.global.u32 [%0], %1;"
                                 :: "l"(&g_done), "r"(0u) : "memory");
                    asm volatile("st.release.gpu.global.u32 [%0], %1;"
                                 :: "l"(&g_bar_phase), "r"(phase + 1) : "memory");
                    released = true;
                }
            }
            if (!released) {
                unsigned cur;
                do {
                    asm volatile("ld.global.acquire.gpu.u32 %0, [%1];"
                                 : "=r"(cur) : "l"(&g_bar_phase) : "memory");
                } while (cur == phase);
            }
        }
        __syncthreads();
        phase++;
    }
}

// ---- final FC + softmax ----
__global__ void k_fc(const float* __restrict__ fcw, const float* __restrict__ fcb,
                     float* __restrict__ out) {
    __shared__ float logits[64][2];
    int tid = threadIdx.x;
    int b = tid >> 1, c = tid & 1;
    const float* h2 = g_h2T[(T - 1) & 1];
    float acc = __ldg(fcb + c);
    for (int k = 0; k < 512; k++)
        acc = fmaf(h2[k * 64 + b], __ldg(fcw + c * 512 + k), acc);
    logits[b][c] = acc;
    __syncthreads();
    if (c == 0) {
        float l0 = logits[b][0], l1 = logits[b][1];
        float m = fmaxf(l0, l1);
        float e0 = expf(l0 - m), e1 = expf(l1 - m);
        float s = e0 + e1;
        out[b * 2 + 0] = e0 / s;
        out[b * 2 + 1] = e1 / s;
    }
}

extern "C" void kernel_launch(void* const* d_in, const int* in_sizes, int n_in,
                              void* d_out, int out_size) {
    const float* x    = (const float*)d_in[0];
    const float* Wih0 = (const float*)d_in[1];
    const float* Whh0 = (const float*)d_in[2];
    const float* bih0 = (const float*)d_in[3];
    const float* bhh0 = (const float*)d_in[4];
    const float* Wih1 = (const float*)d_in[5];
    const float* Whh1 = (const float*)d_in[6];
    const float* bih1 = (const float*)d_in[7];
    const float* bhh1 = (const float*)d_in[8];
    const float* fcw  = (const float*)d_in[9];
    const float* fcb  = (const float*)d_in[10];
    float* out = (float*)d_out;

    cudaFuncSetAttribute(k_xproj, cudaFuncAttributeMaxDynamicSharedMemorySize, 196608);
    cudaFuncSetAttribute(k_recur, cudaFuncAttributeMaxDynamicSharedMemorySize, 98304);

    k_zero<<<256, 256>>>();
    k_transpose<<<4096, 256>>>(x);
    k_xproj<<<dim3(2048, 4), 256, 196608>>>(Wih0, bih0, bhh0);
    k_recur<<<G_BLOCKS, 256, 98304>>>(Whh0, Wih1, Whh1, bih1, bhh1);
    k_fc<<<1, 128>>>(fcw, fcb, out);
}

// round 9
// speedup vs baseline: 1.0774x; 1.0401x over previous
#include <cuda_runtime.h>
#include <math.h>

#define T 2048
#define B 64
#define H 512
#define D 256
#define G_BLOCKS 96
#define NITER (T + 2)

__device__ float g_xT[(size_t)T * D * B];
__device__ float g_xw0T[(size_t)T * H * B];
__device__ float g_h1T[2][H * B];
__device__ float g_h2T[2][H * B];
__device__ float g_zT[2][H * B];
__device__ unsigned g_cnt[3 * 32];
__device__ unsigned g_done;
__device__ unsigned g_bar_phase;

__device__ __forceinline__ void lds_v2u64(unsigned addr, unsigned long long& a,
                                          unsigned long long& b) {
    asm volatile("ld.shared.v2.u64 {%0,%1}, [%2];" : "=l"(a), "=l"(b) : "r"(addr));
}
__device__ __forceinline__ void lds_u64(unsigned addr, unsigned long long& a) {
    asm volatile("ld.shared.u64 %0, [%1];" : "=l"(a) : "r"(addr));
}
__device__ __forceinline__ void sts_u64(unsigned addr, unsigned long long v) {
    asm volatile("st.shared.u64 [%0], %1;" :: "r"(addr), "l"(v));
}
#define FMA2(acc, w, h) \
    asm("fma.rn.f32x2 %0, %1, %2, %0;" : "+l"(acc) : "l"(w), "l"(h))
__device__ __forceinline__ unsigned long long add2(unsigned long long a,
                                                   unsigned long long b) {
    unsigned long long d;
    asm("add.rn.f32x2 %0, %1, %2;" : "=l"(d) : "l"(a), "l"(b));
    return d;
}
__device__ __forceinline__ float2 unpack2(unsigned long long v) {
    float2 r;
    asm("mov.b64 {%0,%1}, %2;" : "=f"(r.x), "=f"(r.y) : "l"(v));
    return r;
}
__device__ __forceinline__ float tanh_fast(float v) {
    asm("tanh.approx.f32 %0, %0;" : "+f"(v));
    return v;
}

__global__ void k_zero() {
    int idx = blockIdx.x * 256 + threadIdx.x;
    if (idx < 2 * H * B) {
        ((float*)g_h1T)[idx] = 0.0f;
        ((float*)g_h2T)[idx] = 0.0f;
    }
}

__global__ void k_transpose(const float* __restrict__ x) {
    size_t n = (size_t)T * D * B;
    size_t stride = (size_t)gridDim.x * blockDim.x;
    for (size_t o = (size_t)blockIdx.x * blockDim.x + threadIdx.x; o < n; o += stride) {
        int b = (int)(o & 63);
        int d = (int)((o >> 6) & 255);
        int t = (int)(o >> 14);
        g_xT[o] = __ldg(x + ((((size_t)b * T + t) << 8) | d));
    }
}

__global__ void __launch_bounds__(256) k_xproj(const float* __restrict__ Wih0,
                                               const float* __restrict__ bih0,
                                               const float* __restrict__ bhh0) {
    extern __shared__ float sm[];
    float* sw = sm;
    float* sx = sm + 128 * 256;
    int t = blockIdx.x, hq = blockIdx.y;
    int tid = threadIdx.x;
    int bgrp = tid & 15, hsub = tid >> 4;
    {
        const float4* s4 = (const float4*)(Wih0 + (size_t)hq * 128 * 256);
        float4* d4 = (float4*)sw;
        #pragma unroll
        for (int r = 0; r < 32; r++) d4[tid + r * 256] = __ldg(s4 + tid + r * 256);
    }
    {
        const float4* s4 = (const float4*)(g_xT + (size_t)t * D * B);
        float4* d4 = (float4*)sx;
        #pragma unroll
        for (int r = 0; r < 16; r++) d4[tid + r * 256] = s4[tid + r * 256];
    }
    __syncthreads();
    float4 acc[8];
    #pragma unroll
    for (int j = 0; j < 8; j++) {
        int h = hq * 128 + j * 16 + hsub;
        float bv = __ldg(bih0 + h) + __ldg(bhh0 + h);
        acc[j] = make_float4(bv, bv, bv, bv);
    }
    const float4* sx4 = (const float4*)sx;
    #pragma unroll 4
    for (int k = 0; k < 256; k++) {
        float4 hv = sx4[k * 16 + bgrp];
        #pragma unroll
        for (int j = 0; j < 8; j++) {
            float w = sw[(j * 16 + hsub) * 256 + k];
            acc[j].x = fmaf(w, hv.x, acc[j].x);
            acc[j].y = fmaf(w, hv.y, acc[j].y);
            acc[j].z = fmaf(w, hv.z, acc[j].z);
            acc[j].w = fmaf(w, hv.w, acc[j].w);
        }
    }
    #pragma unroll
    for (int j = 0; j < 8; j++) {
        int h = hq * 128 + j * 16 + hsub;
        *((float4*)(g_xw0T + ((size_t)t * H + h) * B) + bgrp) = acc[j];
    }
}

// ---- persistent 3-stage recurrence: 512 thr, warp-uniform k ----
// block = 32 rows x 32 batches. ks=tid>>5 (32-k seg), rg -> 4 rows, bg -> 8 b.
// Weight granule (k, rp) at k*256 + s*16, s = (rp>>1)|((rp&1)<<3)  [bijective:
// even rp -> slots 0..7, odd rp -> slots 8..15; each weight LDS.128 covers all
// 32 banks in one phase]. hbuf/red 64KB aliased.
__global__ void __launch_bounds__(512, 1) k_recur(const float* __restrict__ Whh0,
                                                  const float* __restrict__ Wih1,
                                                  const float* __restrict__ Whh1,
                                                  const float* __restrict__ bih1,
                                                  const float* __restrict__ bhh1) {
    extern __shared__ char smb[];
    const unsigned HB = 131072u;

    int stage = blockIdx.x >> 5;
    int sub = blockIdx.x & 31;
    int rowblk = sub >> 1, bhalf = sub & 1;
    int h0 = rowblk * 32;
    int tid = threadIdx.x;
    int ks = tid >> 5;
    int lane = tid & 31;
    int rg = lane >> 2, bg = lane & 3;

    // ---- prestage weights once (bijective rotation swizzle) ----
    const float* Wsrc = (stage == 0) ? Whh0 : (stage == 1) ? Wih1 : Whh1;
    {
        const float* Wr = Wsrc + (size_t)h0 * 512;
        #pragma unroll
        for (int r = 0; r < 8; r++) {
            int idx = tid + r * 512;            // 0..4095 float4
            int row = idx >> 7, k4 = idx & 127;
            float4 v = __ldg((const float4*)(Wr + (size_t)row * 512) + k4);
            int rp = row >> 1, lo = row & 1;
            int s = (rp >> 1) | ((rp & 1) << 3);   // FIXED: bijection
            float vv[4] = {v.x, v.y, v.z, v.w};
            #pragma unroll
            for (int q = 0; q < 4; q++)
                *(float2*)(smb + (k4 * 4 + q) * 256 + s * 16 + lo * 8) =
                    make_float2(vv[q], vv[q]);
        }
    }
    unsigned smem_u = (unsigned)__cvta_generic_to_shared(smb);
    // rp0 = 2rg (even) -> slot rg ; rp1 = 2rg+1 (odd) -> slot 8+rg
    unsigned s1off = (unsigned)(rg * 16);
    unsigned s2off = (unsigned)((8 + rg) * 16);
    unsigned wseg0 = smem_u + (unsigned)(ks * 32) * 256;
    unsigned hseg0 = smem_u + HB + (unsigned)(ks * 32) * 128 + (unsigned)(bg * 32);

    int o = tid;
    int orow = o >> 4, obp = o & 15;
    int hg = h0 + orow;
    float bias = 0.0f;
    if (stage == 1) bias = __ldg(bih1 + hg) + __ldg(bhh1 + hg);
    unsigned rbase = smem_u + HB +
        (unsigned)(((o >> 4) * 16 + (((o & 15) + (o >> 6)) & 15)) * 8);

    unsigned phase;
    asm volatile("ld.global.acquire.gpu.u32 %0, [%1];" : "=r"(phase) : "l"(&g_bar_phase) : "memory");
    __syncthreads();

    for (int i = 0; i < NITER; i++) {
        bool active = (stage == 0) ? (i < T) : (stage == 1) ? (i >= 1 && i <= T) : (i >= 2);
        if (active) {
            int t = i - stage;
            const float* src = (stage == 0) ? g_h1T[(t - 1) & 1]
                             : (stage == 1) ? g_h1T[t & 1]
                                            : g_h2T[(t - 1) & 1];
            const float4* s4 = (const float4*)src;

            float4 pf[8];
            #pragma unroll
            for (int r = 0; r < 8; r++) {
                int m = tid + r * 512;
                pf[r] = __ldcg(s4 + (m >> 3) * 16 + bhalf * 8 + (m & 7));
            }
            float2 ex;
            if (stage == 0)
                ex = __ldcg((const float2*)(g_xw0T + ((size_t)t * H + hg) * B + bhalf * 32) + obp);
            else if (stage == 2)
                ex = __ldcg((const float2*)(g_zT[t & 1] + hg * B + bhalf * 32) + obp);
            else
                ex = make_float2(bias, bias);
            #pragma unroll
            for (int r = 0; r < 8; r++) {
                int m = tid + r * 512;
                *(float4*)(smb + HB + (m >> 3) * 128 + (m & 7) * 16) = pf[r];
            }
            __syncthreads();

            unsigned long long acc[16];
            #pragma unroll
            for (int j = 0; j < 16; j++) acc[j] = 0;
            unsigned wa = wseg0, ha = hseg0;
            #pragma unroll 8
            for (int kk = 0; kk < 32; kk++) {
                unsigned long long w0, w1, w2, w3, hA, hB2, hC, hD;
                lds_v2u64(wa + s1off, w0, w1);   // rows 4rg, 4rg+1
                lds_v2u64(wa + s2off, w2, w3);   // rows 4rg+2, 4rg+3
                lds_v2u64(ha, hA, hB2);          // bp 4bg, 4bg+1
                lds_v2u64(ha + 16, hC, hD);      // bp 4bg+2, 4bg+3
                FMA2(acc[0],  w0, hA); FMA2(acc[1],  w0, hB2);
                FMA2(acc[2],  w0, hC); FMA2(acc[3],  w0, hD);
                FMA2(acc[4],  w1, hA); FMA2(acc[5],  w1, hB2);
                FMA2(acc[6],  w1, hC); FMA2(acc[7],  w1, hD);
                FMA2(acc[8],  w2, hA); FMA2(acc[9],  w2, hB2);
                FMA2(acc[10], w2, hC); FMA2(acc[11], w2, hD);
                FMA2(acc[12], w3, hA); FMA2(acc[13], w3, hB2);
                FMA2(acc[14], w3, hC); FMA2(acc[15], w3, hD);
                wa += 256; ha += 128;
            }
            __syncthreads();   // hbuf dead -> red aliases

            #pragma unroll
            for (int r = 0; r < 4; r++) {
                #pragma unroll
                for (int p = 0; p < 4; p++) {
                    int oo = (rg * 4 + r) * 16 + bg * 4 + p;
                    unsigned a = smem_u + HB + (unsigned)(ks * 4096 +
                        ((oo >> 4) * 16 + (((oo & 15) + (oo >> 6)) & 15)) * 8);
                    sts_u64(a, acc[r * 4 + p]);
                }
            }
            __syncthreads();

            unsigned long long sa = 0, sb = 0;
            #pragma unroll
            for (int j = 0; j < 16; j += 2) {
                unsigned long long q0, q1;
                lds_u64(rbase + (unsigned)(j * 4096), q0);
                lds_u64(rbase + (unsigned)((j + 1) * 4096), q1);
                sa = add2(sa, q0);
                sb = add2(sb, q1);
            }
            float2 f = unpack2(add2(sa, sb));
            f.x += ex.x; f.y += ex.y;
            if (stage != 1) { f.x = tanh_fast(f.x); f.y = tanh_fast(f.y); }
            float* dst = (stage == 0) ? g_h1T[t & 1] : (stage == 1) ? g_zT[t & 1] : g_h2T[t & 1];
            __stcg((float2*)(dst + hg * B + bhalf * 32) + obp, f);
        }
        // ---- two-level release/acquire grid barrier ----
        __syncthreads();
        if (tid == 0) {
            unsigned prev;
            asm volatile("atom.release.gpu.global.add.u32 %0, [%1], %2;"
                         : "=r"(prev) : "l"(&g_cnt[stage * 32]), "r"(1u) : "memory");
            bool released = false;
            if (prev == 31) {
                asm volatile("st.relaxed.gpu.global.u32 [%0], %1;"
                             :: "l"(&g_cnt[stage * 32]), "r"(0u) : "memory");
                unsigned p2;
                asm volatile("atom.acq_rel.gpu.global.add.u32 %0, [%1], %2;"
                             : "=r"(p2) : "l"(&g_done), "r"(1u) : "memory");
                if (p2 == 2) {
                    asm volatile("st.relaxed.gpu.global.u32 [%0], %1;"
                                 :: "l"(&g_done), "r"(0u) : "memory");
                    asm volatile("st.release.gpu.global.u32 [%0], %1;"
                                 :: "l"(&g_bar_phase), "r"(phase + 1) : "memory");
                    released = true;
                }
            }
            if (!released) {
                unsigned cur;
                do {
                    asm volatile("ld.global.acquire.gpu.u32 %0, [%1];"
                                 : "=r"(cur) : "l"(&g_bar_phase) : "memory");
                } while (cur == phase);
            }
        }
        __syncthreads();
        phase++;
    }
}

__global__ void k_fc(const float* __restrict__ fcw, const float* __restrict__ fcb,
                     float* __restrict__ out) {
    __shared__ float logits[64][2];
    int tid = threadIdx.x;
    int b = tid >> 1, c = tid & 1;
    const float* h2 = g_h2T[(T - 1) & 1];
    float acc = __ldg(fcb + c);
    for (int k = 0; k < 512; k++)
        acc = fmaf(h2[k * 64 + b], __ldg(fcw + c * 512 + k), acc);
    logits[b][c] = acc;
    __syncthreads();
    if (c == 0) {
        float l0 = logits[b][0], l1 = logits[b][1];
        float m = fmaxf(l0, l1);
        float e0 = expf(l0 - m), e1 = expf(l1 - m);
        float s = e0 + e1;
        out[b * 2 + 0] = e0 / s;
        out[b * 2 + 1] = e1 / s;
    }
}

extern "C" void kernel_launch(void* const* d_in, const int* in_sizes, int n_in,
                              void* d_out, int out_size) {
    const float* x    = (const float*)d_in[0];
    const float* Wih0 = (const float*)d_in[1];
    const float* Whh0 = (const float*)d_in[2];
    const float* bih0 = (const float*)d_in[3];
    const float* bhh0 = (const float*)d_in[4];
    const float* Wih1 = (const float*)d_in[5];
    const float* Whh1 = (const float*)d_in[6];
    const float* bih1 = (const float*)d_in[7];
    const float* bhh1 = (const float*)d_in[8];
    const float* fcw  = (const float*)d_in[9];
    const float* fcb  = (const float*)d_in[10];
    float* out = (float*)d_out;

    cudaFuncSetAttribute(k_xproj, cudaFuncAttributeMaxDynamicSharedMemorySize, 196608);
    cudaFuncSetAttribute(k_recur, cudaFuncAttributeMaxDynamicSharedMemorySize, 196608);

    k_zero<<<256, 256>>>();
    k_transpose<<<4096, 256>>>(x);
    k_xproj<<<dim3(2048, 4), 256, 196608>>>(Wih0, bih0, bhh0);
    k_recur<<<G_BLOCKS, 512, 196608>>>(Whh0, Wih1, Whh1, bih1, bhh1);
    k_fc<<<1, 128>>>(fcw, fcb, out);
}

// round 10
// speedup vs baseline: 1.1345x; 1.0530x over previous
#include <cuda_runtime.h>
#include <math.h>

#define T 2048
#define B 64
#define H 512
#define D 256
#define G_BLOCKS 96
#define NITER (T + 2)

__device__ float g_xT[(size_t)T * D * B];
__device__ float g_xw0T[(size_t)T * H * B];
__device__ float g_h1T[2][H * B];
__device__ float g_h2T[2][H * B];
__device__ float g_zT[2][H * B];
__device__ unsigned g_arr[3 * 32];   // per-stage monotonic arrival counters (128B apart)
__device__ unsigned g_done;          // monotonic stage-completion counter

__device__ __forceinline__ void lds_v2u64(unsigned addr, unsigned long long& a,
                                          unsigned long long& b) {
    asm volatile("ld.shared.v2.u64 {%0,%1}, [%2];" : "=l"(a), "=l"(b) : "r"(addr));
}
__device__ __forceinline__ void lds_u64(unsigned addr, unsigned long long& a) {
    asm volatile("ld.shared.u64 %0, [%1];" : "=l"(a) : "r"(addr));
}
__device__ __forceinline__ void sts_u64(unsigned addr, unsigned long long v) {
    asm volatile("st.shared.u64 [%0], %1;" :: "r"(addr), "l"(v));
}
#define FMA2(acc, w, h) \
    asm("fma.rn.f32x2 %0, %1, %2, %0;" : "+l"(acc) : "l"(w), "l"(h))
__device__ __forceinline__ unsigned long long add2(unsigned long long a,
                                                   unsigned long long b) {
    unsigned long long d;
    asm("add.rn.f32x2 %0, %1, %2;" : "=l"(d) : "l"(a), "l"(b));
    return d;
}
__device__ __forceinline__ float2 unpack2(unsigned long long v) {
    float2 r;
    asm("mov.b64 {%0,%1}, %2;" : "=f"(r.x), "=f"(r.y) : "l"(v));
    return r;
}
__device__ __forceinline__ float tanh_fast(float v) {
    asm("tanh.approx.f32 %0, %0;" : "+f"(v));
    return v;
}

// ---- zero recurrent state AND barrier counters (every launch/replay) ----
__global__ void k_zero() {
    int idx = blockIdx.x * 256 + threadIdx.x;
    if (idx < 2 * H * B) {
        ((float*)g_h1T)[idx] = 0.0f;
        ((float*)g_h2T)[idx] = 0.0f;
    }
    if (blockIdx.x == 0 && threadIdx.x < 3) g_arr[threadIdx.x * 32] = 0u;
    if (blockIdx.x == 0 && threadIdx.x == 3) g_done = 0u;
}

__global__ void k_transpose(const float* __restrict__ x) {
    size_t n = (size_t)T * D * B;
    size_t stride = (size_t)gridDim.x * blockDim.x;
    for (size_t o = (size_t)blockIdx.x * blockDim.x + threadIdx.x; o < n; o += stride) {
        int b = (int)(o & 63);
        int d = (int)((o >> 6) & 255);
        int t = (int)(o >> 14);
        g_xT[o] = __ldg(x + ((((size_t)b * T + t) << 8) | d));
    }
}

__global__ void __launch_bounds__(256) k_xproj(const float* __restrict__ Wih0,
                                               const float* __restrict__ bih0,
                                               const float* __restrict__ bhh0) {
    extern __shared__ float sm[];
    float* sw = sm;
    float* sx = sm + 128 * 256;
    int t = blockIdx.x, hq = blockIdx.y;
    int tid = threadIdx.x;
    int bgrp = tid & 15, hsub = tid >> 4;
    {
        const float4* s4 = (const float4*)(Wih0 + (size_t)hq * 128 * 256);
        float4* d4 = (float4*)sw;
        #pragma unroll
        for (int r = 0; r < 32; r++) d4[tid + r * 256] = __ldg(s4 + tid + r * 256);
    }
    {
        const float4* s4 = (const float4*)(g_xT + (size_t)t * D * B);
        float4* d4 = (float4*)sx;
        #pragma unroll
        for (int r = 0; r < 16; r++) d4[tid + r * 256] = s4[tid + r * 256];
    }
    __syncthreads();
    float4 acc[8];
    #pragma unroll
    for (int j = 0; j < 8; j++) {
        int h = hq * 128 + j * 16 + hsub;
        float bv = __ldg(bih0 + h) + __ldg(bhh0 + h);
        acc[j] = make_float4(bv, bv, bv, bv);
    }
    const float4* sx4 = (const float4*)sx;
    #pragma unroll 4
    for (int k = 0; k < 256; k++) {
        float4 hv = sx4[k * 16 + bgrp];
        #pragma unroll
        for (int j = 0; j < 8; j++) {
            float w = sw[(j * 16 + hsub) * 256 + k];
            acc[j].x = fmaf(w, hv.x, acc[j].x);
            acc[j].y = fmaf(w, hv.y, acc[j].y);
            acc[j].z = fmaf(w, hv.z, acc[j].z);
            acc[j].w = fmaf(w, hv.w, acc[j].w);
        }
    }
    #pragma unroll
    for (int j = 0; j < 8; j++) {
        int h = hq * 128 + j * 16 + hsub;
        *((float4*)(g_xw0T + ((size_t)t * H + h) * B) + bgrp) = acc[j];
    }
}

// ---- persistent 3-stage recurrence (R9 body) + monotonic REDG barrier ----
__global__ void __launch_bounds__(512, 1) k_recur(const float* __restrict__ Whh0,
                                                  const float* __restrict__ Wih1,
                                                  const float* __restrict__ Whh1,
                                                  const float* __restrict__ bih1,
                                                  const float* __restrict__ bhh1) {
    extern __shared__ char smb[];
    const unsigned HB = 131072u;

    int stage = blockIdx.x >> 5;
    int sub = blockIdx.x & 31;
    int rowblk = sub >> 1, bhalf = sub & 1;
    int h0 = rowblk * 32;
    int tid = threadIdx.x;
    int ks = tid >> 5;
    int lane = tid & 31;
    int rg = lane >> 2, bg = lane & 3;

    const float* Wsrc = (stage == 0) ? Whh0 : (stage == 1) ? Wih1 : Whh1;
    {
        const float* Wr = Wsrc + (size_t)h0 * 512;
        #pragma unroll
        for (int r = 0; r < 8; r++) {
            int idx = tid + r * 512;
            int row = idx >> 7, k4 = idx & 127;
            float4 v = __ldg((const float4*)(Wr + (size_t)row * 512) + k4);
            int rp = row >> 1, lo = row & 1;
            int s = (rp >> 1) | ((rp & 1) << 3);
            float vv[4] = {v.x, v.y, v.z, v.w};
            #pragma unroll
            for (int q = 0; q < 4; q++)
                *(float2*)(smb + (k4 * 4 + q) * 256 + s * 16 + lo * 8) =
                    make_float2(vv[q], vv[q]);
        }
    }
    unsigned smem_u = (unsigned)__cvta_generic_to_shared(smb);
    unsigned s1off = (unsigned)(rg * 16);
    unsigned s2off = (unsigned)((8 + rg) * 16);
    unsigned wseg0 = smem_u + (unsigned)(ks * 32) * 256;
    unsigned hseg0 = smem_u + HB + (unsigned)(ks * 32) * 128 + (unsigned)(bg * 32);

    int o = tid;
    int orow = o >> 4, obp = o & 15;
    int hg = h0 + orow;
    float bias = 0.0f;
    if (stage == 1) bias = __ldg(bih1 + hg) + __ldg(bhh1 + hg);
    unsigned rbase = smem_u + HB +
        (unsigned)(((o >> 4) * 16 + (((o & 15) + (o >> 6)) & 15)) * 8);

    __syncthreads();

    for (int i = 0; i < NITER; i++) {
        bool active = (stage == 0) ? (i < T) : (stage == 1) ? (i >= 1 && i <= T) : (i >= 2);
        if (active) {
            int t = i - stage;
            const float* src = (stage == 0) ? g_h1T[(t - 1) & 1]
                             : (stage == 1) ? g_h1T[t & 1]
                                            : g_h2T[(t - 1) & 1];
            const float4* s4 = (const float4*)src;

            float4 pf[8];
            #pragma unroll
            for (int r = 0; r < 8; r++) {
                int m = tid + r * 512;
                pf[r] = __ldcg(s4 + (m >> 3) * 16 + bhalf * 8 + (m & 7));
            }
            float2 ex;
            if (stage == 0)
                ex = __ldcg((const float2*)(g_xw0T + ((size_t)t * H + hg) * B + bhalf * 32) + obp);
            else if (stage == 2)
                ex = __ldcg((const float2*)(g_zT[t & 1] + hg * B + bhalf * 32) + obp);
            else
                ex = make_float2(bias, bias);
            #pragma unroll
            for (int r = 0; r < 8; r++) {
                int m = tid + r * 512;
                *(float4*)(smb + HB + (m >> 3) * 128 + (m & 7) * 16) = pf[r];
            }
            __syncthreads();

            unsigned long long acc[16];
            #pragma unroll
            for (int j = 0; j < 16; j++) acc[j] = 0;
            unsigned wa = wseg0, ha = hseg0;
            #pragma unroll 8
            for (int kk = 0; kk < 32; kk++) {
                unsigned long long w0, w1, w2, w3, hA, hB2, hC, hD;
                lds_v2u64(wa + s1off, w0, w1);
                lds_v2u64(wa + s2off, w2, w3);
                lds_v2u64(ha, hA, hB2);
                lds_v2u64(ha + 16, hC, hD);
                FMA2(acc[0],  w0, hA); FMA2(acc[1],  w0, hB2);
                FMA2(acc[2],  w0, hC); FMA2(acc[3],  w0, hD);
                FMA2(acc[4],  w1, hA); FMA2(acc[5],  w1, hB2);
                FMA2(acc[6],  w1, hC); FMA2(acc[7],  w1, hD);
                FMA2(acc[8],  w2, hA); FMA2(acc[9],  w2, hB2);
                FMA2(acc[10], w2, hC); FMA2(acc[11], w2, hD);
                FMA2(acc[12], w3, hA); FMA2(acc[13], w3, hB2);
                FMA2(acc[14], w3, hC); FMA2(acc[15], w3, hD);
                wa += 256; ha += 128;
            }
            __syncthreads();   // hbuf dead -> red aliases

            #pragma unroll
            for (int r = 0; r < 4; r++) {
                #pragma unroll
                for (int p = 0; p < 4; p++) {
                    int oo = (rg * 4 + r) * 16 + bg * 4 + p;
                    unsigned a = smem_u + HB + (unsigned)(ks * 4096 +
                        ((oo >> 4) * 16 + (((oo & 15) + (oo >> 6)) & 15)) * 8);
                    sts_u64(a, acc[r * 4 + p]);
                }
            }
            __syncthreads();

            unsigned long long sa = 0, sb = 0;
            #pragma unroll
            for (int j = 0; j < 16; j += 2) {
                unsigned long long q0, q1;
                lds_u64(rbase + (unsigned)(j * 4096), q0);
                lds_u64(rbase + (unsigned)((j + 1) * 4096), q1);
                sa = add2(sa, q0);
                sb = add2(sb, q1);
            }
            float2 f = unpack2(add2(sa, sb));
            f.x += ex.x; f.y += ex.y;
            if (stage != 1) { f.x = tanh_fast(f.x); f.y = tanh_fast(f.y); }
            float* dst = (stage == 0) ? g_h1T[t & 1] : (stage == 1) ? g_zT[t & 1] : g_h2T[t & 1];
            __stcg((float2*)(dst + hg * B + bhalf * 32) + obp, f);
        }
        // ---- monotonic REDG grid barrier ----
        __syncthreads();
        if (tid == 0) {
            unsigned target = (unsigned)(i + 1);
            // arrive on this stage's counter (no-return reduction, release)
            asm volatile("red.release.gpu.global.add.u32 [%0], %1;"
                         :: "l"(&g_arr[stage * 32]), "r"(1u) : "memory");
            if (sub == 0) {
                // stage releaser: wait for all 32 arrivals, then bump g_done
                unsigned c;
                do {
                    asm volatile("ld.global.acquire.gpu.u32 %0, [%1];"
                                 : "=r"(c) : "l"(&g_arr[stage * 32]) : "memory");
                } while (c < 32u * target);
                asm volatile("red.release.gpu.global.add.u32 [%0], %1;"
                             :: "l"(&g_done), "r"(1u) : "memory");
            }
            // all blocks: wait for all 3 stages done
            unsigned d;
            do {
                asm volatile("ld.global.acquire.gpu.u32 %0, [%1];"
                             : "=r"(d) : "l"(&g_done) : "memory");
            } while (d < 3u * target);
        }
        __syncthreads();
    }
}

__global__ void k_fc(const float* __restrict__ fcw, const float* __restrict__ fcb,
                     float* __restrict__ out) {
    __shared__ float logits[64][2];
    int tid = threadIdx.x;
    int b = tid >> 1, c = tid & 1;
    const float* h2 = g_h2T[(T - 1) & 1];
    float acc = __ldg(fcb + c);
    for (int k = 0; k < 512; k++)
        acc = fmaf(h2[k * 64 + b], __ldg(fcw + c * 512 + k), acc);
    logits[b][c] = acc;
    __syncthreads();
    if (c == 0) {
        float l0 = logits[b][0], l1 = logits[b][1];
        float m = fmaxf(l0, l1);
        float e0 = expf(l0 - m), e1 = expf(l1 - m);
        float s = e0 + e1;
        out[b * 2 + 0] = e0 / s;
        out[b * 2 + 1] = e1 / s;
    }
}

extern "C" void kernel_launch(void* const* d_in, const int* in_sizes, int n_in,
                              void* d_out, int out_size) {
    const float* x    = (const float*)d_in[0];
    const float* Wih0 = (const float*)d_in[1];
    const float* Whh0 = (const float*)d_in[2];
    const float* bih0 = (const float*)d_in[3];
    const float* bhh0 = (const float*)d_in[4];
    const float* Wih1 = (const float*)d_in[5];
    const float* Whh1 = (const float*)d_in[6];
    const float* bih1 = (const float*)d_in[7];
    const float* bhh1 = (const float*)d_in[8];
    const float* fcw  = (const float*)d_in[9];
    const float* fcb  = (const float*)d_in[10];
    float* out = (float*)d_out;

    cudaFuncSetAttribute(k_xproj, cudaFuncAttributeMaxDynamicSharedMemorySize, 196608);
    cudaFuncSetAttribute(k_recur, cudaFuncAttributeMaxDynamicSharedMemorySize, 196608);

    k_zero<<<256, 256>>>();
    k_transpose<<<4096, 256>>>(x);
    k_xproj<<<dim3(2048, 4), 256, 196608>>>(Wih0, bih0, bhh0);
    k_recur<<<G_BLOCKS, 512, 196608>>>(Whh0, Wih1, Whh1, bih1, bhh1);
    k_fc<<<1, 128>>>(fcw, fcb, out);
}

// round 11
// speedup vs baseline: 1.3225x; 1.1658x over previous
#include <cuda_runtime.h>
#include <math.h>

#define T 2048
#define B 64
#define H 512
#define D 256
#define G_BLOCKS 96
#define NITER (T + 2)

__device__ float g_xT[(size_t)T * D * B];
__device__ float g_xw0T[(size_t)T * H * B];
__device__ float g_h1T[4][H * B];    // ring, slot = t & 3
__device__ float g_h2T[4][H * B];
__device__ float g_zT[4][H * B];
__device__ unsigned g_arr[3 * 32];   // per-stage monotonic arrival counters (128B apart)

__device__ __forceinline__ void lds_v2u64(unsigned addr, unsigned long long& a,
                                          unsigned long long& b) {
    asm volatile("ld.shared.v2.u64 {%0,%1}, [%2];" : "=l"(a), "=l"(b) : "r"(addr));
}
__device__ __forceinline__ void lds_u64(unsigned addr, unsigned long long& a) {
    asm volatile("ld.shared.u64 %0, [%1];" : "=l"(a) : "r"(addr));
}
__device__ __forceinline__ void sts_u64(unsigned addr, unsigned long long v) {
    asm volatile("st.shared.u64 [%0], %1;" :: "r"(addr), "l"(v));
}
#define FMA2(acc, w, h) \
    asm("fma.rn.f32x2 %0, %1, %2, %0;" : "+l"(acc) : "l"(w), "l"(h))
__device__ __forceinline__ unsigned long long add2(unsigned long long a,
                                                   unsigned long long b) {
    unsigned long long d;
    asm("add.rn.f32x2 %0, %1, %2;" : "=l"(d) : "l"(a), "l"(b));
    return d;
}
__device__ __forceinline__ float2 unpack2(unsigned long long v) {
    float2 r;
    asm("mov.b64 {%0,%1}, %2;" : "=f"(r.x), "=f"(r.y) : "l"(v));
    return r;
}
__device__ __forceinline__ float tanh_fast(float v) {
    asm("tanh.approx.f32 %0, %0;" : "+f"(v));
    return v;
}
__device__ __forceinline__ void poll_ge(const unsigned* p, unsigned target) {
    unsigned c;
    do {
        asm volatile("ld.global.acquire.gpu.u32 %0, [%1];" : "=r"(c) : "l"(p) : "memory");
    } while ((int)(c - target) < 0);
}

// ---- zero recurrent state rings AND counters (every launch/replay) ----
__global__ void k_zero() {
    int idx = blockIdx.x * 256 + threadIdx.x;
    if (idx < 4 * H * B) {
        ((float*)g_h1T)[idx] = 0.0f;
        ((float*)g_h2T)[idx] = 0.0f;
    }
    if (blockIdx.x == 0 && threadIdx.x < 3) g_arr[threadIdx.x * 32] = 0u;
}

__global__ void k_transpose(const float* __restrict__ x) {
    size_t n = (size_t)T * D * B;
    size_t stride = (size_t)gridDim.x * blockDim.x;
    for (size_t o = (size_t)blockIdx.x * blockDim.x + threadIdx.x; o < n; o += stride) {
        int b = (int)(o & 63);
        int d = (int)((o >> 6) & 255);
        int t = (int)(o >> 14);
        g_xT[o] = __ldg(x + ((((size_t)b * T + t) << 8) | d));
    }
}

__global__ void __launch_bounds__(256) k_xproj(const float* __restrict__ Wih0,
                                               const float* __restrict__ bih0,
                                               const float* __restrict__ bhh0) {
    extern __shared__ float sm[];
    float* sw = sm;
    float* sx = sm + 128 * 256;
    int t = blockIdx.x, hq = blockIdx.y;
    int tid = threadIdx.x;
    int bgrp = tid & 15, hsub = tid >> 4;
    {
        const float4* s4 = (const float4*)(Wih0 + (size_t)hq * 128 * 256);
        float4* d4 = (float4*)sw;
        #pragma unroll
        for (int r = 0; r < 32; r++) d4[tid + r * 256] = __ldg(s4 + tid + r * 256);
    }
    {
        const float4* s4 = (const float4*)(g_xT + (size_t)t * D * B);
        float4* d4 = (float4*)sx;
        #pragma unroll
        for (int r = 0; r < 16; r++) d4[tid + r * 256] = s4[tid + r * 256];
    }
    __syncthreads();
    float4 acc[8];
    #pragma unroll
    for (int j = 0; j < 8; j++) {
        int h = hq * 128 + j * 16 + hsub;
        float bv = __ldg(bih0 + h) + __ldg(bhh0 + h);
        acc[j] = make_float4(bv, bv, bv, bv);
    }
    const float4* sx4 = (const float4*)sx;
    #pragma unroll 4
    for (int k = 0; k < 256; k++) {
        float4 hv = sx4[k * 16 + bgrp];
        #pragma unroll
        for (int j = 0; j < 8; j++) {
            float w = sw[(j * 16 + hsub) * 256 + k];
            acc[j].x = fmaf(w, hv.x, acc[j].x);
            acc[j].y = fmaf(w, hv.y, acc[j].y);
            acc[j].z = fmaf(w, hv.z, acc[j].z);
            acc[j].w = fmaf(w, hv.w, acc[j].w);
        }
    }
    #pragma unroll
    for (int j = 0; j < 8; j++) {
        int h = hq * 128 + j * 16 + hsub;
        *((float4*)(g_xw0T + ((size_t)t * H + h) * B) + bgrp) = acc[j];
    }
}

// ---- persistent decoupled 3-stage pipeline (R9 body, per-stage flow sync) ----
__global__ void __launch_bounds__(512, 1) k_recur(const float* __restrict__ Whh0,
                                                  const float* __restrict__ Wih1,
                                                  const float* __restrict__ Whh1,
                                                  const float* __restrict__ bih1,
                                                  const float* __restrict__ bhh1) {
    extern __shared__ char smb[];
    const unsigned HB = 131072u;

    int stage = blockIdx.x >> 5;
    int sub = blockIdx.x & 31;
    int rowblk = sub >> 1, bhalf = sub & 1;
    int h0 = rowblk * 32;
    int tid = threadIdx.x;
    int ks = tid >> 5;
    int lane = tid & 31;
    int rg = lane >> 2, bg = lane & 3;

    const float* Wsrc = (stage == 0) ? Whh0 : (stage == 1) ? Wih1 : Whh1;
    {
        const float* Wr = Wsrc + (size_t)h0 * 512;
        #pragma unroll
        for (int r = 0; r < 8; r++) {
            int idx = tid + r * 512;
            int row = idx >> 7, k4 = idx & 127;
            float4 v = __ldg((const float4*)(Wr + (size_t)row * 512) + k4);
            int rp = row >> 1, lo = row & 1;
            int s = (rp >> 1) | ((rp & 1) << 3);
            float vv[4] = {v.x, v.y, v.z, v.w};
            #pragma unroll
            for (int q = 0; q < 4; q++)
                *(float2*)(smb + (k4 * 4 + q) * 256 + s * 16 + lo * 8) =
                    make_float2(vv[q], vv[q]);
        }
    }
    unsigned smem_u = (unsigned)__cvta_generic_to_shared(smb);
    unsigned s1off = (unsigned)(rg * 16);
    unsigned s2off = (unsigned)((8 + rg) * 16);
    unsigned wseg0 = smem_u + (unsigned)(ks * 32) * 256;
    unsigned hseg0 = smem_u + HB + (unsigned)(ks * 32) * 128 + (unsigned)(bg * 32);

    int o = tid;
    int orow = o >> 4, obp = o & 15;
    int hg = h0 + orow;
    float bias = 0.0f;
    if (stage == 1) bias = __ldg(bih1 + hg) + __ldg(bhh1 + hg);
    unsigned rbase = smem_u + HB +
        (unsigned)(((o >> 4) * 16 + (((o & 15) + (o >> 6)) & 15)) * 8);

    __syncthreads();

    for (int i = 0; i < NITER; i++) {
        // ---- flow-control waits (two polls in parallel) ----
        // s0@i: arr0>=32i (own h1 recurrence), arr1>=32(i-2) (h1 ring guard)
        // s1@i: arr0>=32i (h1[i-1] ready),      arr2>=32(i-2) (z ring guard)
        // s2@i: arr2>=32i (own h2 recurrence),  arr1>=32i     (z[i-2] ready)
        {
            unsigned tA, tB;
            const unsigned *pA, *pB;
            if (stage == 0)      { pA = &g_arr[0];  tA = 32u * i;
                                   pB = &g_arr[32]; tB = (i >= 2) ? 32u * (i - 2) : 0u; }
            else if (stage == 1) { pA = &g_arr[0];  tA = 32u * i;
                                   pB = &g_arr[64]; tB = (i >= 2) ? 32u * (i - 2) : 0u; }
            else                 { pA = &g_arr[64]; tA = 32u * i;
                                   pB = &g_arr[32]; tB = 32u * i; }
            if (tid == 0) poll_ge(pA, tA);
            else if (tid == 32) poll_ge(pB, tB);
        }
        __syncthreads();

        bool active = (stage == 0) ? (i < T) : (stage == 1) ? (i >= 1 && i <= T) : (i >= 2);
        if (active) {
            int t = i - stage;
            const float* src = (stage == 0) ? g_h1T[(t - 1) & 3]
                             : (stage == 1) ? g_h1T[t & 3]
                                            : g_h2T[(t - 1) & 3];
            const float4* s4 = (const float4*)src;

            float4 pf[8];
            #pragma unroll
            for (int r = 0; r < 8; r++) {
                int m = tid + r * 512;
                pf[r] = __ldcg(s4 + (m >> 3) * 16 + bhalf * 8 + (m & 7));
            }
            float2 ex;
            if (stage == 0)
                ex = __ldcg((const float2*)(g_xw0T + ((size_t)t * H + hg) * B + bhalf * 32) + obp);
            else if (stage == 2)
                ex = __ldcg((const float2*)(g_zT[t & 3] + hg * B + bhalf * 32) + obp);
            else
                ex = make_float2(bias, bias);
            #pragma unroll
            for (int r = 0; r < 8; r++) {
                int m = tid + r * 512;
                *(float4*)(smb + HB + (m >> 3) * 128 + (m & 7) * 16) = pf[r];
            }
            __syncthreads();

            unsigned long long acc[16];
            #pragma unroll
            for (int j = 0; j < 16; j++) acc[j] = 0;
            unsigned wa = wseg0, ha = hseg0;
            #pragma unroll 8
            for (int kk = 0; kk < 32; kk++) {
                unsigned long long w0, w1, w2, w3, hA, hB2, hC, hD;
                lds_v2u64(wa + s1off, w0, w1);
                lds_v2u64(wa + s2off, w2, w3);
                lds_v2u64(ha, hA, hB2);
                lds_v2u64(ha + 16, hC, hD);
                FMA2(acc[0],  w0, hA); FMA2(acc[1],  w0, hB2);
                FMA2(acc[2],  w0, hC); FMA2(acc[3],  w0, hD);
                FMA2(acc[4],  w1, hA); FMA2(acc[5],  w1, hB2);
                FMA2(acc[6],  w1, hC); FMA2(acc[7],  w1, hD);
                FMA2(acc[8],  w2, hA); FMA2(acc[9],  w2, hB2);
                FMA2(acc[10], w2, hC); FMA2(acc[11], w2, hD);
                FMA2(acc[12], w3, hA); FMA2(acc[13], w3, hB2);
                FMA2(acc[14], w3, hC); FMA2(acc[15], w3, hD);
                wa += 256; ha += 128;
            }
            __syncthreads();   // hbuf dead -> red aliases

            #pragma unroll
            for (int r = 0; r < 4; r++) {
                #pragma unroll
                for (int p = 0; p < 4; p++) {
                    int oo = (rg * 4 + r) * 16 + bg * 4 + p;
                    unsigned a = smem_u + HB + (unsigned)(ks * 4096 +
                        ((oo >> 4) * 16 + (((oo & 15) + (oo >> 6)) & 15)) * 8);
                    sts_u64(a, acc[r * 4 + p]);
                }
            }
            __syncthreads();

            unsigned long long sa = 0, sb = 0;
            #pragma unroll
            for (int j = 0; j < 16; j += 2) {
                unsigned long long q0, q1;
                lds_u64(rbase + (unsigned)(j * 4096), q0);
                lds_u64(rbase + (unsigned)((j + 1) * 4096), q1);
                sa = add2(sa, q0);
                sb = add2(sb, q1);
            }
            float2 f = unpack2(add2(sa, sb));
            f.x += ex.x; f.y += ex.y;
            if (stage != 1) { f.x = tanh_fast(f.x); f.y = tanh_fast(f.y); }
            float* dst = (stage == 0) ? g_h1T[t & 3] : (stage == 1) ? g_zT[t & 3] : g_h2T[t & 3];
            __stcg((float2*)(dst + hg * B + bhalf * 32) + obp, f);
        }
        // ---- arrive: one no-return release reduction ----
        __syncthreads();
        if (tid == 0)
            asm volatile("red.release.gpu.global.add.u32 [%0], %1;"
                         :: "l"(&g_arr[stage * 32]), "r"(1u) : "memory");
        __syncthreads();
    }
}

__global__ void k_fc(const float* __restrict__ fcw, const float* __restrict__ fcb,
                     float* __restrict__ out) {
    __shared__ float logits[64][2];
    int tid = threadIdx.x;
    int b = tid >> 1, c = tid & 1;
    const float* h2 = g_h2T[(T - 1) & 3];
    float acc = __ldg(fcb + c);
    for (int k = 0; k < 512; k++)
        acc = fmaf(h2[k * 64 + b], __ldg(fcw + c * 512 + k), acc);
    logits[b][c] = acc;
    __syncthreads();
    if (c == 0) {
        float l0 = logits[b][0], l1 = logits[b][1];
        float m = fmaxf(l0, l1);
        float e0 = expf(l0 - m), e1 = expf(l1 - m);
        float s = e0 + e1;
        out[b * 2 + 0] = e0 / s;
        out[b * 2 + 1] = e1 / s;
    }
}

extern "C" void kernel_launch(void* const* d_in, const int* in_sizes, int n_in,
                              void* d_out, int out_size) {
    const float* x    = (const float*)d_in[0];
    const float* Wih0 = (const float*)d_in[1];
    const float* Whh0 = (const float*)d_in[2];
    const float* bih0 = (const float*)d_in[3];
    const float* bhh0 = (const float*)d_in[4];
    const float* Wih1 = (const float*)d_in[5];
    const float* Whh1 = (const float*)d_in[6];
    const float* bih1 = (const float*)d_in[7];
    const float* bhh1 = (const float*)d_in[8];
    const float* fcw  = (const float*)d_in[9];
    const float* fcb  = (const float*)d_in[10];
    float* out = (float*)d_out;

    cudaFuncSetAttribute(k_xproj, cudaFuncAttributeMaxDynamicSharedMemorySize, 196608);
    cudaFuncSetAttribute(k_recur, cudaFuncAttributeMaxDynamicSharedMemorySize, 196608);

    k_zero<<<512, 256>>>();
    k_transpose<<<4096, 256>>>(x);
    k_xproj<<<dim3(2048, 4), 256, 196608>>>(Wih0, bih0, bhh0);
    k_recur<<<G_BLOCKS, 512, 196608>>>(Whh0, Wih1, Whh1, bih1, bhh1);
    k_fc<<<1, 128>>>(fcw, fcb, out);
}

// round 12
// speedup vs baseline: 1.4048x; 1.0622x over previous
#include <cuda_runtime.h>
#include <math.h>

#define T 2048
#define B 64
#define H 512
#define D 256
#define NITER (T + 2)

__device__ float g_xw0R[8][H * B];   // xw0 ring (L2-resident, 1MB)
__device__ float g_h1T[4][H * B];    // rings, slot = t & 3
__device__ float g_h2T[4][H * B];
__device__ float g_zT[4][H * B];
__device__ unsigned g_arr[4 * 32];   // per-group monotonic arrival counters (128B apart)

__device__ __forceinline__ void lds_v2u64(unsigned addr, unsigned long long& a,
                                          unsigned long long& b) {
    asm volatile("ld.shared.v2.u64 {%0,%1}, [%2];" : "=l"(a), "=l"(b) : "r"(addr));
}
__device__ __forceinline__ void lds_u64(unsigned addr, unsigned long long& a) {
    asm volatile("ld.shared.u64 %0, [%1];" : "=l"(a) : "r"(addr));
}
__device__ __forceinline__ void sts_u64(unsigned addr, unsigned long long v) {
    asm volatile("st.shared.u64 [%0], %1;" :: "r"(addr), "l"(v));
}
#define FMA2(acc, w, h) \
    asm("fma.rn.f32x2 %0, %1, %2, %0;" : "+l"(acc) : "l"(w), "l"(h))
__device__ __forceinline__ unsigned long long add2(unsigned long long a,
                                                   unsigned long long b) {
    unsigned long long d;
    asm("add.rn.f32x2 %0, %1, %2;" : "=l"(d) : "l"(a), "l"(b));
    return d;
}
__device__ __forceinline__ float2 unpack2(unsigned long long v) {
    float2 r;
    asm("mov.b64 {%0,%1}, %2;" : "=f"(r.x), "=f"(r.y) : "l"(v));
    return r;
}
__device__ __forceinline__ float tanh_fast(float v) {
    asm("tanh.approx.f32 %0, %0;" : "+f"(v));
    return v;
}
__device__ __forceinline__ void poll_ge(const unsigned* p, unsigned target) {
    unsigned c;
    do {
        asm volatile("ld.global.acquire.gpu.u32 %0, [%1];" : "=r"(c) : "l"(p) : "memory");
    } while ((int)(c - target) < 0);
}

// ---- zero recurrent state rings AND counters (every launch/replay) ----
__global__ void k_zero() {
    int idx = blockIdx.x * 256 + threadIdx.x;
    if (idx < 4 * H * B) {
        ((float*)g_h1T)[idx] = 0.0f;
        ((float*)g_h2T)[idx] = 0.0f;
    }
    if (blockIdx.x == 0 && threadIdx.x < 4) g_arr[threadIdx.x * 32] = 0u;
}

// ---- persistent decoupled 4-group pipeline ----
// grp 0 (blk  0- 31): h1[t]=tanh(xw0[t] + Whh0 h1[t-1]),  t=i,   K=512
// grp 1 (blk 32- 63): z[t]=bias1 + Wih1 h1[t],            t=i-1, K=512
// grp 2 (blk 64- 95): h2[t]=tanh(z[t] + Whh1 h2[t-1]),    t=i-2, K=512
// grp 3 (blk 96-127): xw0[t]=bias0 + Wih0 x[t],           t=i,   K=256 (free-runs)
__global__ void __launch_bounds__(512, 1) k_recur(
    const float* __restrict__ Whh0, const float* __restrict__ Wih1,
    const float* __restrict__ Whh1, const float* __restrict__ Wih0,
    const float* __restrict__ x,
    const float* __restrict__ bih0, const float* __restrict__ bhh0,
    const float* __restrict__ bih1, const float* __restrict__ bhh1)
{
    extern __shared__ char smb[];
    const unsigned HB = 131072u;
    const unsigned XI = 65536u;      // x intermediate tile (stage 3 only)

    int stage = blockIdx.x >> 5;
    int sub = blockIdx.x & 31;
    int rowblk = sub >> 1, bhalf = sub & 1;
    int h0 = rowblk * 32;
    int tid = threadIdx.x;
    int ks = tid >> 5;
    int lane = tid & 31;
    int rg = lane >> 2, bg = lane & 3;

    // ---- prestage weights once (bijective rotation swizzle) ----
    const float* Wsrc = (stage == 0) ? Whh0 : (stage == 1) ? Wih1
                      : (stage == 2) ? Whh1 : Wih0;
    int K = (stage == 3) ? 256 : 512;
    {
        const float* Wr = Wsrc + (size_t)h0 * K;
        int kshift = (stage == 3) ? 6 : 7;
        int kmask = (K / 4) - 1;
        int nld = (stage == 3) ? 4 : 8;
        for (int r = 0; r < nld; r++) {
            int idx = tid + r * 512;
            int row = idx >> kshift, k4 = idx & kmask;
            float4 v = __ldg((const float4*)(Wr + (size_t)row * K) + k4);
            int rp = row >> 1, lo = row & 1;
            int s = (rp >> 1) | ((rp & 1) << 3);
            float vv[4] = {v.x, v.y, v.z, v.w};
            #pragma unroll
            for (int q = 0; q < 4; q++)
                *(float2*)(smb + (k4 * 4 + q) * 256 + s * 16 + lo * 8) =
                    make_float2(vv[q], vv[q]);
        }
    }
    unsigned smem_u = (unsigned)__cvta_generic_to_shared(smb);
    unsigned s1off = (unsigned)(rg * 16);
    unsigned s2off = (unsigned)((8 + rg) * 16);
    int nkw = (stage == 3) ? 16 : 32;   // k per warp
    unsigned wseg0 = smem_u + (unsigned)(ks * nkw) * 256;
    unsigned hseg0 = smem_u + HB + (unsigned)(ks * nkw) * 128 + (unsigned)(bg * 32);

    int o = tid;
    int orow = o >> 4, obp = o & 15;
    int hg = h0 + orow;
    float bias = 0.0f;
    if (stage == 1) bias = __ldg(bih1 + hg) + __ldg(bhh1 + hg);
    if (stage == 3) bias = __ldg(bih0 + hg) + __ldg(bhh0 + hg);
    unsigned rbase = smem_u + HB +
        (unsigned)(((o >> 4) * 16 + (((o & 15) + (o >> 6)) & 15)) * 8);

    __syncthreads();

    for (int i = 0; i < NITER; i++) {
        // ---- upfront waits (gate input reads) ----
        const unsigned *upA = 0, *upB = 0, *dfp = 0;
        unsigned tA = 0, tB = 0, tD = 0;
        if (stage == 0) {
            upA = &g_arr[0];  tA = 32u * i;                 // own h1 recurrence
            upB = &g_arr[96]; tB = 32u * (i + 1);           // xw0[i] ready
            dfp = &g_arr[32]; tD = (i >= 2) ? 32u * (i - 2) : 0u;  // h1 ring guard
        } else if (stage == 1) {
            upA = &g_arr[0];  tA = 32u * i;                 // h1[i-1] ready
            dfp = &g_arr[64]; tD = (i >= 2) ? 32u * (i - 2) : 0u;  // z ring guard
        } else if (stage == 2) {
            upA = &g_arr[64]; tA = 32u * i;                 // own h2 recurrence
            upB = &g_arr[32]; tB = 32u * i;                 // z[i-2] ready
        } else {
            dfp = &g_arr[0];  tD = (i >= 8) ? 32u * (i - 7) : 0u;  // xw0 ring guard
        }
        if (tid == 0 && upA) poll_ge(upA, tA);
        else if (tid == 32 && upB) poll_ge(upB, tB);
        __syncthreads();

        bool active = (stage == 0) ? (i < T)
                    : (stage == 1) ? (i >= 1 && i <= T)
                    : (stage == 2) ? (i >= 2)
                                   : (i < T);
        if (active) {
            int t = i - ((stage == 1) ? 1 : (stage == 2) ? 2 : 0);

            // ---- stage input vector into hbuf [k][granule] ----
            if (stage != 3) {
                const float* src = (stage == 0) ? g_h1T[(t - 1) & 3]
                                 : (stage == 1) ? g_h1T[t & 3]
                                                : g_h2T[(t - 1) & 3];
                const float4* s4 = (const float4*)src;
                float4 pf[8];
                #pragma unroll
                for (int r = 0; r < 8; r++) {
                    int m = tid + r * 512;
                    pf[r] = __ldcg(s4 + (m >> 3) * 16 + bhalf * 8 + (m & 7));
                }
                #pragma unroll
                for (int r = 0; r < 8; r++) {
                    int m = tid + r * 512;
                    *(float4*)(smb + HB + (m >> 3) * 128 + (m & 7) * 16) = pf[r];
                }
            } else {
                // phase A: x[b][t][:] -> padded [b][d] tile (coalesced LDG)
                #pragma unroll
                for (int r = 0; r < 4; r++) {
                    int f = tid + r * 512;
                    int bl = f >> 6, d4 = f & 63;
                    float4 v = __ldg((const float4*)(x +
                        ((size_t)(bhalf * 32 + bl) * T + t) * 256) + d4);
                    *(float4*)(smb + XI + bl * 1040 + d4 * 16) = v;
                }
                __syncthreads();
                // phase B: transpose tile -> hbuf granules [k][c]
                #pragma unroll
                for (int r = 0; r < 4; r++) {
                    int m = tid + r * 512;
                    int k = m >> 3, c = m & 7;
                    float4 g;
                    g.x = *(float*)(smb + XI + (4 * c + 0) * 1040 + k * 4);
                    g.y = *(float*)(smb + XI + (4 * c + 1) * 1040 + k * 4);
                    g.z = *(float*)(smb + XI + (4 * c + 2) * 1040 + k * 4);
                    g.w = *(float*)(smb + XI + (4 * c + 3) * 1040 + k * 4);
                    *(float4*)(smb + HB + k * 128 + c * 16) = g;
                }
            }
            float2 ex;
            if (stage == 0)
                ex = __ldcg((const float2*)(g_xw0R[i & 7] + hg * B + bhalf * 32) + obp);
            else if (stage == 2)
                ex = __ldcg((const float2*)(g_zT[t & 3] + hg * B + bhalf * 32) + obp);
            else
                ex = make_float2(bias, bias);
            __syncthreads();

            // ---- body: nkw k x (4 one-phase LDS.128 + 16 FFMA2) ----
            unsigned long long acc[16];
            #pragma unroll
            for (int j = 0; j < 16; j++) acc[j] = 0;
            unsigned wa = wseg0, ha = hseg0;
            #pragma unroll 8
            for (int kk = 0; kk < nkw; kk++) {
                unsigned long long w0, w1, w2, w3, hA, hB2, hC, hD;
                lds_v2u64(wa + s1off, w0, w1);
                lds_v2u64(wa + s2off, w2, w3);
                lds_v2u64(ha, hA, hB2);
                lds_v2u64(ha + 16, hC, hD);
                FMA2(acc[0],  w0, hA); FMA2(acc[1],  w0, hB2);
                FMA2(acc[2],  w0, hC); FMA2(acc[3],  w0, hD);
                FMA2(acc[4],  w1, hA); FMA2(acc[5],  w1, hB2);
                FMA2(acc[6],  w1, hC); FMA2(acc[7],  w1, hD);
                FMA2(acc[8],  w2, hA); FMA2(acc[9],  w2, hB2);
                FMA2(acc[10], w2, hC); FMA2(acc[11], w2, hD);
                FMA2(acc[12], w3, hA); FMA2(acc[13], w3, hB2);
                FMA2(acc[14], w3, hC); FMA2(acc[15], w3, hD);
                wa += 256; ha += 128;
            }
            __syncthreads();   // hbuf dead -> red aliases

            #pragma unroll
            for (int r = 0; r < 4; r++) {
                #pragma unroll
                for (int p = 0; p < 4; p++) {
                    int oo = (rg * 4 + r) * 16 + bg * 4 + p;
                    unsigned a = smem_u + HB + (unsigned)(ks * 4096 +
                        ((oo >> 4) * 16 + (((oo & 15) + (oo >> 6)) & 15)) * 8);
                    sts_u64(a, acc[r * 4 + p]);
                }
            }
            // deferred ring-guard poll (overlaps with partial stores)
            if (tid == 64 && dfp) poll_ge(dfp, tD);
            __syncthreads();

            unsigned long long sa = 0, sb = 0;
            #pragma unroll
            for (int j = 0; j < 16; j += 2) {
                unsigned long long q0, q1;
                lds_u64(rbase + (unsigned)(j * 4096), q0);
                lds_u64(rbase + (unsigned)((j + 1) * 4096), q1);
                sa = add2(sa, q0);
                sb = add2(sb, q1);
            }
            float2 f = unpack2(add2(sa, sb));
            f.x += ex.x; f.y += ex.y;
            if (stage == 0 || stage == 2) { f.x = tanh_fast(f.x); f.y = tanh_fast(f.y); }
            float* dst = (stage == 0) ? g_h1T[t & 3]
                       : (stage == 1) ? g_zT[t & 3]
                       : (stage == 2) ? g_h2T[t & 3]
                                      : g_xw0R[t & 7];
            __stcg((float2*)(dst + hg * B + bhalf * 32) + obp, f);
        }
        // ---- arrive (trailing barrier merged into next iter's top barrier) ----
        __syncthreads();
        if (tid == 0)
            asm volatile("red.release.gpu.global.add.u32 [%0], %1;"
                         :: "l"(&g_arr[stage * 32]), "r"(1u) : "memory");
    }
}

__global__ void k_fc(const float* __restrict__ fcw, const float* __restrict__ fcb,
                     float* __restrict__ out) {
    __shared__ float logits[64][2];
    int tid = threadIdx.x;
    int b = tid >> 1, c = tid & 1;
    const float* h2 = g_h2T[(T - 1) & 3];
    float acc = __ldg(fcb + c);
    for (int k = 0; k < 512; k++)
        acc = fmaf(h2[k * 64 + b], __ldg(fcw + c * 512 + k), acc);
    logits[b][c] = acc;
    __syncthreads();
    if (c == 0) {
        float l0 = logits[b][0], l1 = logits[b][1];
        float m = fmaxf(l0, l1);
        float e0 = expf(l0 - m), e1 = expf(l1 - m);
        float s = e0 + e1;
        out[b * 2 + 0] = e0 / s;
        out[b * 2 + 1] = e1 / s;
    }
}

extern "C" void kernel_launch(void* const* d_in, const int* in_sizes, int n_in,
                              void* d_out, int out_size) {
    const float* x    = (const float*)d_in[0];
    const float* Wih0 = (const float*)d_in[1];
    const float* Whh0 = (const float*)d_in[2];
    const float* bih0 = (const float*)d_in[3];
    const float* bhh0 = (const float*)d_in[4];
    const float* Wih1 = (const float*)d_in[5];
    const float* Whh1 = (const float*)d_in[6];
    const float* bih1 = (const float*)d_in[7];
    const float* bhh1 = (const float*)d_in[8];
    const float* fcw  = (const float*)d_in[9];
    const float* fcb  = (const float*)d_in[10];
    float* out = (float*)d_out;

    cudaFuncSetAttribute(k_recur, cudaFuncAttributeMaxDynamicSharedMemorySize, 196608);

    k_zero<<<512, 256>>>();
    k_recur<<<128, 512, 196608>>>(Whh0, Wih1, Whh1, Wih0, x,
                                  bih0, bhh0, bih1, bhh1);
    k_fc<<<1, 128>>>(fcw, fcb, out);
}